// round 15
// baseline (speedup 1.0000x reference)
#include <cuda_runtime.h>
#include <cuda_bf16.h>
#include <math.h>
#include <stdint.h>

// Problem constants
#define S_LEN 4096
#define HID_D 2304
#define NH_Q 8
#define N_KV 4
#define HD_H 256
#define SWIN 2048
#define QO_W (NH_Q * HD_H)   // 2048
#define KV_W (N_KV * HD_H)   // 1024

// fused QKV fp32 output: cols [0,2048)=q, [2048,3072)=k  (v goes direct to bf16)
__device__ float g_qkv[S_LEN * 4096];
// split bf16 operands
__device__ __nv_bfloat16 g_xh [S_LEN * HID_D],  g_xl [S_LEN * HID_D];
__device__ __nv_bfloat16 g_wqh[QO_W * HID_D],   g_wql[QO_W * HID_D];
__device__ __nv_bfloat16 g_wkh[KV_W * HID_D],   g_wkl[KV_W * HID_D];
__device__ __nv_bfloat16 g_wvh[KV_W * HID_D],   g_wvl[KV_W * HID_D];
__device__ __nv_bfloat16 g_woh[HID_D * QO_W],   g_wol[HID_D * QO_W];
__device__ __nv_bfloat16 g_qh [S_LEN * QO_W],   g_ql [S_LEN * QO_W];
__device__ __nv_bfloat16 g_kh [S_LEN * KV_W],   g_kl [S_LEN * KV_W];
__device__ __nv_bfloat16 g_vh [S_LEN * KV_W],   g_vl [S_LEN * KV_W];
__device__ __nv_bfloat16 g_aoh[S_LEN * QO_W],   g_aol[S_LEN * QO_W];

// ===========================================================================
// helpers
// ===========================================================================
__device__ __forceinline__ uint32_t smem_u32(const void* p) {
    uint32_t a;
    asm("{ .reg .u64 t; cvta.to.shared.u64 t, %1; cvt.u32.u64 %0, t; }" : "=r"(a) : "l"(p));
    return a;
}

__device__ __forceinline__ uint32_t pack_bf16_rn(float lo, float hi) {
    uint32_t r;
    asm("cvt.rn.bf16x2.f32 %0, %1, %2;" : "=r"(r) : "f"(hi), "f"(lo));
    return r;
}

__device__ __forceinline__ void split4(float4 v, uint32_t& h0, uint32_t& h1,
                                       uint32_t& l0, uint32_t& l1) {
    uint32_t bx = __float_as_uint(v.x), by = __float_as_uint(v.y);
    uint32_t bz = __float_as_uint(v.z), bw = __float_as_uint(v.w);
    h0 = __byte_perm(bx, by, 0x7632);
    h1 = __byte_perm(bz, bw, 0x7632);
    float lx = v.x - __uint_as_float(bx & 0xFFFF0000u);
    float ly = v.y - __uint_as_float(by & 0xFFFF0000u);
    float lz = v.z - __uint_as_float(bz & 0xFFFF0000u);
    float lw = v.w - __uint_as_float(bw & 0xFFFF0000u);
    l0 = pack_bf16_rn(lx, ly);
    l1 = pack_bf16_rn(lz, lw);
}

__device__ __forceinline__ void cvt_store(uint32_t dst_hi, uint32_t dst_lo, float4 v) {
    uint32_t h0, h1, l0, l1;
    split4(v, h0, h1, l0, l1);
    asm volatile("st.shared.v2.b32 [%0], {%1,%2};" :: "r"(dst_hi), "r"(h0), "r"(h1) : "memory");
    asm volatile("st.shared.v2.b32 [%0], {%1,%2};" :: "r"(dst_lo), "r"(l0), "r"(l1) : "memory");
}

__device__ __forceinline__ void split2(float a, float b, uint32_t& uh, uint32_t& ul) {
    uint32_t ba = __float_as_uint(a), bb = __float_as_uint(b);
    uh = __byte_perm(ba, bb, 0x7632);
    float ra = a - __uint_as_float(ba & 0xFFFF0000u);
    float rb = b - __uint_as_float(bb & 0xFFFF0000u);
    ul = pack_bf16_rn(ra, rb);
}

#define LDSM4(R0, R1, R2, R3, ADDR) \
    asm volatile("ldmatrix.sync.aligned.m8n8.x4.shared.b16 {%0,%1,%2,%3}, [%4];" \
        : "=r"(R0), "=r"(R1), "=r"(R2), "=r"(R3) : "r"(ADDR))

#define LDSM4T(R0, R1, R2, R3, ADDR) \
    asm volatile("ldmatrix.sync.aligned.m8n8.x4.trans.shared.b16 {%0,%1,%2,%3}, [%4];" \
        : "=r"(R0), "=r"(R1), "=r"(R2), "=r"(R3) : "r"(ADDR))

#define MMA16816(CC, A0, A1, A2, A3, B0, B1) \
    asm volatile("mma.sync.aligned.m16n8k16.row.col.f32.bf16.bf16.f32 " \
        "{%0,%1,%2,%3}, {%4,%5,%6,%7}, {%8,%9}, {%0,%1,%2,%3};" \
        : "+f"((CC)[0]), "+f"((CC)[1]), "+f"((CC)[2]), "+f"((CC)[3]) \
        : "r"(A0), "r"(A1), "r"(A2), "r"(A3), "r"(B0), "r"(B1))

#define CPA16(DST, SRC) \
    asm volatile("cp.async.ca.shared.global [%0], [%1], 16;" :: "r"(DST), "l"(SRC) : "memory")
#define CPA_COMMIT() asm volatile("cp.async.commit_group;" ::: "memory")
template<int NN> __device__ __forceinline__ void cpa_wait() {
    asm volatile("cp.async.wait_group %0;" :: "n"(NN) : "memory");
}

#define STS128(ADDR, V) \
    asm volatile("st.shared.v4.b32 [%0], {%1,%2,%3,%4};" \
        :: "r"(ADDR), "r"((V).x), "r"((V).y), "r"((V).z), "r"((V).w) : "memory")

// ===========================================================================
// fused split kernel: all 5 fp32 inputs -> bf16 hi/lo arrays in ONE launch
// ===========================================================================
#define SEG0 2359296                // x:  4096*2304/4
#define SEG1 (SEG0 + 1179648)       // wq: 2048*2304/4
#define SEG2 (SEG1 + 589824)        // wk: 1024*2304/4
#define SEG3 (SEG2 + 589824)        // wv
#define SEG4 (SEG3 + 1179648)       // wo: 2304*2048/4

__global__ void split_all(
    const float4* __restrict__ x,  const float4* __restrict__ wq,
    const float4* __restrict__ wk, const float4* __restrict__ wv,
    const float4* __restrict__ wo,
    uint2* xh, uint2* xl, uint2* qh, uint2* ql, uint2* kh, uint2* kl,
    uint2* vh, uint2* vl, uint2* oh, uint2* ol)
{
    int i = blockIdx.x * blockDim.x + threadIdx.x;
    if (i >= SEG4) return;
    const float4* s; uint2 *h, *l; int j;
    if (i < SEG0)      { s = x;  h = xh; l = xl; j = i; }
    else if (i < SEG1) { s = wq; h = qh; l = ql; j = i - SEG0; }
    else if (i < SEG2) { s = wk; h = kh; l = kl; j = i - SEG1; }
    else if (i < SEG3) { s = wv; h = vh; l = vl; j = i - SEG2; }
    else               { s = wo; h = oh; l = ol; j = i - SEG3; }
    float4 v = s[j];
    uint32_t h0, h1, l0, l1;
    split4(v, h0, h1, l0, l1);
    h[j] = make_uint2(h0, h1);
    l[j] = make_uint2(l0, l1);
}

// ===========================================================================
// HMMA GEMM (unchanged from R13): 128x128 CTA, BK=64, cp.async 3-stage ring,
// GROUP_M=8 swizzle; QKV segment-select with direct split-v epilogue.
// ===========================================================================
#define GSTAGE  65536
#define GOFF_AL 16384
#define GOFF_BH 32768
#define GOFF_BL 49152

template<bool QKV>
__global__ void __launch_bounds__(256) gemm_b16(
    const __nv_bfloat16* __restrict__ Ah, const __nv_bfloat16* __restrict__ Al,
    const __nv_bfloat16* __restrict__ B0h, const __nv_bfloat16* __restrict__ B0l,
    const __nv_bfloat16* __restrict__ B1h, const __nv_bfloat16* __restrict__ B1l,
    const __nv_bfloat16* __restrict__ B2h, const __nv_bfloat16* __restrict__ B2l,
    float* __restrict__ C, __nv_bfloat16* __restrict__ Ch, __nv_bfloat16* __restrict__ Cl,
    int N, int K)
{
    extern __shared__ unsigned char dsm[];
    uint32_t sb = smem_u32(dsm);
    sb = (sb + 1023u) & ~1023u;

    const int tid  = threadIdx.x;
    const int wid  = tid >> 5;
    const int lane = tid & 31;
    const int wm   = (wid >> 2) * 64;
    const int wn   = (wid & 3) * 32;

    int m0, n0;
    {
        const int nbx = gridDim.x, nby = gridDim.y;
        int pid = blockIdx.y * nbx + blockIdx.x;
        int group = 8 * nbx;
        int gid = pid / group;
        int first_m = gid * 8;
        int gsz = nby - first_m; if (gsz > 8) gsz = 8;
        m0 = (first_m + (pid % group) % gsz) * 128;
        n0 = ((pid % group) / gsz) * 128;
    }
    const int NI = K >> 6;

    const __nv_bfloat16 *Bh, *Bl;
    int nb;
    if (!QKV || n0 < 2048)      { Bh = B0h; Bl = B0l; nb = n0; }
    else if (n0 < 3072)         { Bh = B1h; Bl = B1l; nb = n0 - 2048; }
    else                        { Bh = B2h; Bl = B2l; nb = n0 - 3072; }

    float acc[4][4][4];
#pragma unroll
    for (int mt = 0; mt < 4; mt++)
#pragma unroll
        for (int nt = 0; nt < 4; nt++)
#pragma unroll
            for (int q = 0; q < 4; q++) acc[mt][nt][q] = 0.f;

    const int a_r = (lane & 7) + ((lane >> 3) & 1) * 8;
    const int a_c = (lane >> 4) & 1;
    const int b_r = (lane & 7) + ((lane >> 4) & 1) * 8;
    const int b_c = (lane >> 3) & 1;

    int cr[4], cc[4];
    uint32_t cof[4];
#pragma unroll
    for (int k = 0; k < 4; k++) {
        int idx = tid + k * 256;
        cr[k] = idx >> 3; cc[k] = idx & 7;
        cof[k] = cr[k] * 128 + ((cc[k] ^ (cr[k] & 7)) << 4);
    }

    auto issue = [&](int k0, uint32_t base) {
        const char* pAh = (const char*)Ah + ((size_t)m0 * K + k0) * 2;
        const char* pAl = (const char*)Al + ((size_t)m0 * K + k0) * 2;
        const char* pBh = (const char*)Bh + ((size_t)nb * K + k0) * 2;
        const char* pBl = (const char*)Bl + ((size_t)nb * K + k0) * 2;
#pragma unroll
        for (int k = 0; k < 4; k++) {
            size_t so = (size_t)cr[k] * K * 2 + cc[k] * 16;
            CPA16(base + cof[k],           pAh + so);
            CPA16(base + GOFF_AL + cof[k], pAl + so);
            CPA16(base + GOFF_BH + cof[k], pBh + so);
            CPA16(base + GOFF_BL + cof[k], pBl + so);
        }
        CPA_COMMIT();
    };

    issue(0, sb);
    issue(64, sb + GSTAGE);

    int st = 0;
    for (int it = 0; it < NI; it++) {
        if (it + 1 < NI) cpa_wait<1>(); else cpa_wait<0>();
        __syncthreads();
        if (it + 2 < NI) {
            int st2 = st + 2; if (st2 >= 3) st2 -= 3;
            issue((it + 2) * 64, sb + st2 * GSTAGE);
        }
        const uint32_t sAh = sb + st * GSTAGE;
        const uint32_t sAl = sAh + GOFF_AL;
        const uint32_t sBh = sAh + GOFF_BH;
        const uint32_t sBl = sAh + GOFF_BL;

#pragma unroll
        for (int ks = 0; ks < 4; ks++) {
            const int cb = ks * 2;
            uint32_t ah[4][4], bh[4][2], bl[4][2];

#pragma unroll
            for (int mt = 0; mt < 4; mt++) {
                int r = wm + mt * 16 + a_r;
                uint32_t ad = sAh + r * 128 + (((cb + a_c) ^ (r & 7)) << 4);
                LDSM4(ah[mt][0], ah[mt][1], ah[mt][2], ah[mt][3], ad);
            }
#pragma unroll
            for (int np = 0; np < 2; np++) {
                int r = wn + np * 16 + b_r;
                uint32_t bd = sBh + r * 128 + (((cb + b_c) ^ (r & 7)) << 4);
                LDSM4(bh[2 * np][0], bh[2 * np][1], bh[2 * np + 1][0], bh[2 * np + 1][1], bd);
            }
#pragma unroll
            for (int mt = 0; mt < 4; mt++)
#pragma unroll
                for (int nt = 0; nt < 4; nt++)
                    MMA16816(acc[mt][nt], ah[mt][0], ah[mt][1], ah[mt][2], ah[mt][3],
                             bh[nt][0], bh[nt][1]);
#pragma unroll
            for (int np = 0; np < 2; np++) {
                int r = wn + np * 16 + b_r;
                uint32_t bd = sBl + r * 128 + (((cb + b_c) ^ (r & 7)) << 4);
                LDSM4(bl[2 * np][0], bl[2 * np][1], bl[2 * np + 1][0], bl[2 * np + 1][1], bd);
            }
#pragma unroll
            for (int mt = 0; mt < 4; mt++)
#pragma unroll
                for (int nt = 0; nt < 4; nt++)
                    MMA16816(acc[mt][nt], ah[mt][0], ah[mt][1], ah[mt][2], ah[mt][3],
                             bl[nt][0], bl[nt][1]);
#pragma unroll
            for (int mt = 0; mt < 4; mt++) {
                int r = wm + mt * 16 + a_r;
                uint32_t ad = sAl + r * 128 + (((cb + a_c) ^ (r & 7)) << 4);
                LDSM4(ah[mt][0], ah[mt][1], ah[mt][2], ah[mt][3], ad);
            }
#pragma unroll
            for (int mt = 0; mt < 4; mt++)
#pragma unroll
                for (int nt = 0; nt < 4; nt++)
                    MMA16816(acc[mt][nt], ah[mt][0], ah[mt][1], ah[mt][2], ah[mt][3],
                             bh[nt][0], bh[nt][1]);
        }
        if (++st >= 3) st -= 3;
    }

    const int lr = lane >> 2;
    const int lc = (lane & 3) * 2;
    if (QKV && n0 >= 3072) {
#pragma unroll
        for (int mt = 0; mt < 4; mt++) {
#pragma unroll
            for (int nt = 0; nt < 4; nt++) {
                size_t idx = (size_t)(m0 + wm + mt * 16 + lr) * KV_W +
                             (n0 - 3072) + wn + nt * 8 + lc;
                uint32_t uh, ul;
                split2(acc[mt][nt][0], acc[mt][nt][1], uh, ul);
                *(uint32_t*)(Ch + idx) = uh;
                *(uint32_t*)(Cl + idx) = ul;
                split2(acc[mt][nt][2], acc[mt][nt][3], uh, ul);
                *(uint32_t*)(Ch + idx + 8 * (size_t)KV_W) = uh;
                *(uint32_t*)(Cl + idx + 8 * (size_t)KV_W) = ul;
            }
        }
    } else {
#pragma unroll
        for (int mt = 0; mt < 4; mt++) {
#pragma unroll
            for (int nt = 0; nt < 4; nt++) {
                float* p = C + (size_t)(m0 + wm + mt * 16 + lr) * N + n0 + wn + nt * 8 + lc;
                *(float2*)p           = make_float2(acc[mt][nt][0], acc[mt][nt][1]);
                *(float2*)(p + 8 * N) = make_float2(acc[mt][nt][2], acc[mt][nt][3]);
            }
        }
    }
}

// ---------------------------------------------------------------------------
// Post-QKV: rope+split for q,k (unchanged from R13).
// ---------------------------------------------------------------------------
__global__ void rope_split_qk(const float* __restrict__ qkv, const int* __restrict__ pos,
                              __nv_bfloat16* __restrict__ qh, __nv_bfloat16* __restrict__ ql,
                              __nv_bfloat16* __restrict__ kh, __nv_bfloat16* __restrict__ kl)
{
    const int TQ = S_LEN * NH_Q * 128;
    const int TK = S_LEN * N_KV * 128;
    int i = blockIdx.x * blockDim.x + threadIdx.x;
    if (i >= TQ + TK) return;

    const float* src;
    __nv_bfloat16 *bh, *bl;
    int s, d;
    float scale;
    if (i < TQ) {
        d = i & 127;
        int hh = (i >> 7) & 7;
        s = i >> 10;
        src = qkv + (size_t)s * 4096 + hh * HD_H;
        bh = qh + (size_t)s * QO_W + hh * HD_H;
        bl = ql + (size_t)s * QO_W + hh * HD_H;
        scale = 0.0625f;
    } else {
        int j = i - TQ;
        d = j & 127;
        int hh = (j >> 7) & 3;
        s = j >> 9;
        src = qkv + (size_t)s * 4096 + 2048 + hh * HD_H;
        bh = kh + (size_t)s * KV_W + hh * HD_H;
        bl = kl + (size_t)s * KV_W + hh * HD_H;
        scale = 1.f;
    }
    float p   = (float)pos[s];
    float inv = powf(10000.f, -(float)d * (1.f / 128.f));
    float ang = p * inv;
    float c, sn;
    sincosf(ang, &sn, &c);
    float x1 = src[d];
    float x2 = src[d + 128];
    float y1 = (x1 * c - x2 * sn) * scale;
    float y2 = (x2 * c + x1 * sn) * scale;

    uint32_t b1 = __float_as_uint(y1), b2 = __float_as_uint(y2);
    *(uint16_t*)(bh + d)       = (uint16_t)(b1 >> 16);
    *(uint16_t*)(bh + d + 128) = (uint16_t)(b2 >> 16);
    bl[d]       = __float2bfloat16(y1 - __uint_as_float(b1 & 0xFFFF0000u));
    bl[d + 128] = __float2bfloat16(y2 - __uint_as_float(b2 & 0xFFFF0000u));
}

// ===========================================================================
// Flash attention on HMMA: 512 threads (16 warps, 4x4 grid), cp.async K/V
// staging (K triple-buffered, V quarters). Softmax passes byte-identical to
// R10 under tid<256 guards. 3-term QK and PV splits.
// ===========================================================================
#define AOFF_QH  0
#define AOFF_QL  32768
#define AOFF_VH  65536
#define AOFF_VL  98304
#define AOFF_KH  131072    // 3 x 8192
#define AOFF_KL  155648    // 3 x 8192
#define AOFF_PBH 180224
#define AOFF_PBL 188416
#define AOFF_PS  196608    // 64*68*4 = 17408
#define AOFF_MS  214016
#define AOFF_LS  214272
#define AOFF_SF  214528
#define AOFF_RED 214784    // 1024
#define ATTN_SMEM_BYTES (215808 + 128)

__global__ void __launch_bounds__(512) attn_mma(
    const __nv_bfloat16* __restrict__ qh, const __nv_bfloat16* __restrict__ ql,
    const __nv_bfloat16* __restrict__ kh, const __nv_bfloat16* __restrict__ kl,
    const __nv_bfloat16* __restrict__ vh, const __nv_bfloat16* __restrict__ vl,
    __nv_bfloat16* __restrict__ aoh, __nv_bfloat16* __restrict__ aol)
{
    extern __shared__ unsigned char asm_raw[];
    uint32_t sb = smem_u32(asm_raw);
    sb = (sb + 127u) & ~127u;
    const uint32_t pad = sb - smem_u32(asm_raw);

    const uint32_t sQh = sb + AOFF_QH,  sQl = sb + AOFF_QL;
    const uint32_t sVh = sb + AOFF_VH,  sVl = sb + AOFF_VL;
    const uint32_t sKh = sb + AOFF_KH,  sKl = sb + AOFF_KL;
    const uint32_t sPh = sb + AOFF_PBH, sPl = sb + AOFF_PBL;
    float* Ps  = (float*)(asm_raw + pad + AOFF_PS);
    float* m_s = (float*)(asm_raw + pad + AOFF_MS);
    float* l_s = (float*)(asm_raw + pad + AOFF_LS);
    float* sf_s= (float*)(asm_raw + pad + AOFF_SF);
    float* red = (float*)(asm_raw + pad + AOFF_RED);

    const int tid  = threadIdx.x;
    const int wid  = tid >> 5;
    const int lane = tid & 31;
    const int wr   = wid >> 2;           // 0..3 -> 16 q-rows
    const int wc   = wid & 3;            // 0..3 -> 16 keys (QK) / 64 dims (PV)
    const int qt   = gridDim.x - 1 - blockIdx.x;
    const int h    = blockIdx.y;
    const int qs   = qt * 64;
    const int kvh  = h >> 1;
    const float CAP = 50.f, INV_CAP2 = 2.f / 50.f;

    const int a_r = (lane & 7) + ((lane >> 3) & 1) * 8;
    const int a_c = (lane >> 4) & 1;
    const int b_r = (lane & 7) + ((lane >> 4) & 1) * 8;
    const int b_c = (lane >> 3) & 1;
    const int lr  = lane >> 2;
    const int lc  = (lane & 3) * 2;

    // ---- load pre-split Q (64 x 256 bf16, already scaled) ----
    {
        const char* qhb = (const char*)(qh + (size_t)qs * QO_W + h * HD_H);
        const char* qlb = (const char*)(ql + (size_t)qs * QO_W + h * HD_H);
#pragma unroll
        for (int i = 0; i < 4; i++) {
            int idx = tid + i * 512;
            int r = idx >> 5, c = idx & 31;
            uint32_t off = r * 512 + ((c ^ (r & 7)) << 4);
            uint4 vh4 = *(const uint4*)(qhb + (size_t)r * QO_W * 2 + c * 16);
            uint4 vl4 = *(const uint4*)(qlb + (size_t)r * QO_W * 2 + c * 16);
            STS128(sQh + off, vh4);
            STS128(sQl + off, vl4);
        }
    }
    if (tid < 64) { m_s[tid] = -1e30f; l_s[tid] = 0.f; }

    // O accumulator: per warp rows wr*16..+16, dims wc*64..+64 -> 8 n8 tiles
    float o[8][4];
#pragma unroll
    for (int nt = 0; nt < 8; nt++)
#pragma unroll
        for (int q = 0; q < 4; q++) o[nt][q] = 0.f;

    const int kt_lo = (qs - (SWIN - 1) > 0 ? qs - (SWIN - 1) : 0) >> 6;
    const __nv_bfloat16* khb0 = kh + kvh * HD_H;
    const __nv_bfloat16* klb0 = kl + kvh * HD_H;
    const __nv_bfloat16* vhb0 = vh + kvh * HD_H;
    const __nv_bfloat16* vlb0 = vl + kvh * HD_H;

    // staging coords: 64 rows x 8 chunks of 16B = 512 -> 1 chunk/thread/array
    const int s_r = tid >> 3, s_c = tid & 7;
    const uint32_t offk_sw = s_r * 128 + ((s_c ^ (s_r & 7)) << 4);

    int kb0 = 0;   // K ring base (mod 3), advances +1 per kt (4 mod 3)

    for (int kt = qt; kt >= kt_lo; kt--) {
        const int ks0 = kt * 64;
        const char* khr = (const char*)(khb0 + (size_t)ks0 * KV_W);
        const char* klr = (const char*)(klb0 + (size_t)ks0 * KV_W);
        const char* vhr = (const char*)(vhb0 + (size_t)ks0 * KV_W);
        const char* vlr = (const char*)(vlb0 + (size_t)ks0 * KV_W);

        auto issue = [&](int dc, int kb) {
            size_t go = (size_t)s_r * (KV_W * 2) + dc * 128 + s_c * 16;
            uint32_t offk = kb * 8192 + offk_sw;
            uint32_t offv = s_r * 512 + (((dc * 8 + s_c) ^ (s_r & 7)) << 4);
            CPA16(sKh + offk, khr + go);
            CPA16(sKl + offk, klr + go);
            CPA16(sVh + offv, vhr + go);
            CPA16(sVl + offv, vlr + go);
            CPA_COMMIT();
        };

        float s[2][4];
#pragma unroll
        for (int nt = 0; nt < 2; nt++)
#pragma unroll
            for (int q = 0; q < 4; q++) s[nt][q] = 0.f;

        __syncthreads();   // prev kt PV / P consumers done before overwriting V
        issue(0, kb0);

#pragma unroll
        for (int dc = 0; dc < 4; dc++) {
            if (dc < 3) {
                int kbn = kb0 + dc + 1; if (kbn >= 3) kbn -= 3; if (kbn >= 3) kbn -= 3;
                issue(dc + 1, kbn);
                cpa_wait<1>();
            } else {
                cpa_wait<0>();
            }
            __syncthreads();   // chunk dc data visible to all

            int kbc = kb0 + dc; if (kbc >= 3) kbc -= 3; if (kbc >= 3) kbc -= 3;
            const uint32_t kB = kbc * 8192;
#pragma unroll
            for (int ks = 0; ks < 4; ks++) {
                const int cbq = dc * 8 + ks * 2;
                const int cbk = ks * 2;
                uint32_t ah[4], al[4], bh[4], bl[4];
                {
                    int r = wr * 16 + a_r;
                    LDSM4(ah[0], ah[1], ah[2], ah[3],
                          sQh + r * 512 + (((cbq + a_c) ^ (r & 7)) << 4));
                    LDSM4(al[0], al[1], al[2], al[3],
                          sQl + r * 512 + (((cbq + a_c) ^ (r & 7)) << 4));
                }
                {
                    int r = wc * 16 + b_r;
                    LDSM4(bh[0], bh[1], bh[2], bh[3],
                          sKh + kB + r * 128 + (((cbk + b_c) ^ (r & 7)) << 4));
                }
                MMA16816(s[0], ah[0], ah[1], ah[2], ah[3], bh[0], bh[1]);
                MMA16816(s[1], ah[0], ah[1], ah[2], ah[3], bh[2], bh[3]);
                MMA16816(s[0], al[0], al[1], al[2], al[3], bh[0], bh[1]);
                MMA16816(s[1], al[0], al[1], al[2], al[3], bh[2], bh[3]);
                {
                    int r = wc * 16 + b_r;
                    LDSM4(bl[0], bl[1], bl[2], bl[3],
                          sKl + kB + r * 128 + (((cbk + b_c) ^ (r & 7)) << 4));
                }
                MMA16816(s[0], ah[0], ah[1], ah[2], ah[3], bl[0], bl[1]);
                MMA16816(s[1], ah[0], ah[1], ah[2], ah[3], bl[2], bl[3]);
            }
        }
        kb0++; if (kb0 >= 3) kb0 -= 3;

        // ---- softcap + mask -> Ps (new warp grid: keys 16 per warp) ----
#pragma unroll
        for (int nt = 0; nt < 2; nt++) {
            int col = wc * 16 + nt * 8 + lc;
            int gj0 = ks0 + col;
#pragma unroll
            for (int half = 0; half < 2; half++) {
                int row = wr * 16 + lr + half * 8;
                int gi = qs + row;
                float t0 = __expf(s[nt][2 * half + 0] * INV_CAP2);
                float t1 = __expf(s[nt][2 * half + 1] * INV_CAP2);
                float sv0 = CAP - __fdividef(2.f * CAP, t0 + 1.f);
                float sv1 = CAP - __fdividef(2.f * CAP, t1 + 1.f);
                bool ok0 = (gj0 <= gi)     && ((gi - gj0) < SWIN);
                bool ok1 = (gj0 + 1 <= gi) && ((gi - gj0 - 1) < SWIN);
                *(float2*)&Ps[row * 68 + col] =
                    make_float2(ok0 ? sv0 : -1e30f, ok1 ? sv1 : -1e30f);
            }
        }
        __syncthreads();

        // ---- row max (R10-verbatim, tid<256) ----
        if (tid < 256) {
            int row = tid >> 2, l4 = tid & 3;
            const float* pr = Ps + row * 68 + l4 * 16;
            float mx = -1e30f;
#pragma unroll
            for (int t = 0; t < 16; t++) mx = fmaxf(mx, pr[t]);
            red[row * 4 + l4] = mx;
        }
        __syncthreads();
        if (tid < 64) {
            float mt = fmaxf(fmaxf(red[tid * 4], red[tid * 4 + 1]),
                             fmaxf(red[tid * 4 + 2], red[tid * 4 + 3]));
            float mo = m_s[tid];
            float mn = fmaxf(mo, mt);
            sf_s[tid] = __expf(mo - mn);
            m_s[tid]  = mn;
        }
        __syncthreads();

        // ---- exp -> P bf16 hi/lo + row sums (R10-verbatim, tid<256) ----
        if (tid < 256) {
            int row = tid >> 2, l4 = tid & 3;
            float mn = m_s[row];
            const float* pr = Ps + row * 68 + l4 * 16;
            float sum = 0.f;
#pragma unroll
            for (int g = 0; g < 4; g++) {
                float e[4];
#pragma unroll
                for (int t = 0; t < 4; t++) {
                    float pv = pr[g * 4 + t];
                    e[t] = (pv < -1e29f) ? 0.f : __expf(pv - mn);
                    sum += e[t];
                }
                uint32_t chunk = l4 * 2 + (g >> 1);
                uint32_t off = row * 128 + ((chunk ^ (row & 7)) << 4) + (g & 1) * 8;
                cvt_store(sPh + off, sPl + off, make_float4(e[0], e[1], e[2], e[3]));
            }
            red[row * 4 + l4] = sum;
        }
        __syncthreads();
        if (tid < 64) {
            l_s[tid] = l_s[tid] * sf_s[tid] +
                       (red[tid * 4] + red[tid * 4 + 1] +
                        red[tid * 4 + 2] + red[tid * 4 + 3]);
        }

        // ---- rescale O ----
        {
            float sfa = sf_s[wr * 16 + lr];
            float sfb = sf_s[wr * 16 + lr + 8];
#pragma unroll
            for (int nt = 0; nt < 8; nt++) {
                o[nt][0] *= sfa; o[nt][1] *= sfa;
                o[nt][2] *= sfb; o[nt][3] *= sfb;
            }
        }

        // ---- O += P V (dims wc*64..+64 per warp) ----
#pragma unroll
        for (int kk = 0; kk < 4; kk++) {
            uint32_t ph[4], pl[4];
            {
                int r = wr * 16 + a_r;
                uint32_t c = kk * 2 + a_c;
                LDSM4(ph[0], ph[1], ph[2], ph[3], sPh + r * 128 + ((c ^ (r & 7)) << 4));
                LDSM4(pl[0], pl[1], pl[2], pl[3], sPl + r * 128 + ((c ^ (r & 7)) << 4));
            }
#pragma unroll
            for (int vp = 0; vp < 4; vp++) {
                int key = kk * 16 + a_r;
                uint32_t chv = wc * 8 + vp * 2 + a_c;
                uint32_t vb[4], vl4[4];
                LDSM4T(vb[0], vb[1], vb[2], vb[3],
                       sVh + key * 512 + ((chv ^ (key & 7)) << 4));
                MMA16816(o[2 * vp],     ph[0], ph[1], ph[2], ph[3], vb[0], vb[1]);
                MMA16816(o[2 * vp + 1], ph[0], ph[1], ph[2], ph[3], vb[2], vb[3]);
                MMA16816(o[2 * vp],     pl[0], pl[1], pl[2], pl[3], vb[0], vb[1]);
                MMA16816(o[2 * vp + 1], pl[0], pl[1], pl[2], pl[3], vb[2], vb[3]);
                LDSM4T(vl4[0], vl4[1], vl4[2], vl4[3],
                       sVl + key * 512 + ((chv ^ (key & 7)) << 4));
                MMA16816(o[2 * vp],     ph[0], ph[1], ph[2], ph[3], vl4[0], vl4[1]);
                MMA16816(o[2 * vp + 1], ph[0], ph[1], ph[2], ph[3], vl4[2], vl4[3]);
            }
        }
    }

    __syncthreads();
    // ---- normalize + split + write bf16 ----
    {
        float inva = 1.f / l_s[wr * 16 + lr];
        float invb = 1.f / l_s[wr * 16 + lr + 8];
        size_t i0 = (size_t)(qs + wr * 16 + lr) * QO_W + h * HD_H + wc * 64;
        size_t i1 = i0 + 8 * (size_t)QO_W;
#pragma unroll
        for (int nt = 0; nt < 8; nt++) {
            uint32_t uh, ul;
            split2(o[nt][0] * inva, o[nt][1] * inva, uh, ul);
            *(uint32_t*)(aoh + i0 + nt * 8 + lc) = uh;
            *(uint32_t*)(aol + i0 + nt * 8 + lc) = ul;
            split2(o[nt][2] * invb, o[nt][3] * invb, uh, ul);
            *(uint32_t*)(aoh + i1 + nt * 8 + lc) = uh;
            *(uint32_t*)(aol + i1 + nt * 8 + lc) = ul;
        }
    }
}

// ---------------------------------------------------------------------------
// Launch
// ---------------------------------------------------------------------------
#define GEMM_DSMEM (3 * GSTAGE + 1024)

extern "C" void kernel_launch(void* const* d_in, const int* in_sizes, int n_in,
                              void* d_out, int out_size)
{
    const float* x   = (const float*)d_in[0];   // [4096, 2304]
    const int*   pos = (const int*)  d_in[1];   // [1, 4096]
    const float* Wq  = (const float*)d_in[2];   // [2048, 2304]
    const float* Wk  = (const float*)d_in[3];   // [1024, 2304]
    const float* Wv  = (const float*)d_in[4];   // [1024, 2304]
    const float* Wo  = (const float*)d_in[5];   // [2304, 2048]
    float* out = (float*)d_out;                 // [4096, 2304]

    float* qkv;
    __nv_bfloat16 *xh, *xl, *wqh, *wql, *wkh, *wkl, *wvh, *wvl, *woh, *wol;
    __nv_bfloat16 *qh, *ql, *kh2, *kl2, *vh, *vl, *aoh, *aol;
    cudaGetSymbolAddress((void**)&qkv, g_qkv);
    cudaGetSymbolAddress((void**)&xh,  g_xh);  cudaGetSymbolAddress((void**)&xl,  g_xl);
    cudaGetSymbolAddress((void**)&wqh, g_wqh); cudaGetSymbolAddress((void**)&wql, g_wql);
    cudaGetSymbolAddress((void**)&wkh, g_wkh); cudaGetSymbolAddress((void**)&wkl, g_wkl);
    cudaGetSymbolAddress((void**)&wvh, g_wvh); cudaGetSymbolAddress((void**)&wvl, g_wvl);
    cudaGetSymbolAddress((void**)&woh, g_woh); cudaGetSymbolAddress((void**)&wol, g_wol);
    cudaGetSymbolAddress((void**)&qh,  g_qh);  cudaGetSymbolAddress((void**)&ql,  g_ql);
    cudaGetSymbolAddress((void**)&kh2, g_kh);  cudaGetSymbolAddress((void**)&kl2, g_kl);
    cudaGetSymbolAddress((void**)&vh,  g_vh);  cudaGetSymbolAddress((void**)&vl,  g_vl);
    cudaGetSymbolAddress((void**)&aoh, g_aoh); cudaGetSymbolAddress((void**)&aol, g_aol);

    cudaFuncSetAttribute(gemm_b16<true>,  cudaFuncAttributeMaxDynamicSharedMemorySize, GEMM_DSMEM);
    cudaFuncSetAttribute(gemm_b16<false>, cudaFuncAttributeMaxDynamicSharedMemorySize, GEMM_DSMEM);
    cudaFuncSetAttribute(attn_mma, cudaFuncAttributeMaxDynamicSharedMemorySize, ATTN_SMEM_BYTES);

    // One fused split of all fp32 inputs
    split_all<<<(SEG4 + 255) / 256, 256>>>(
        (const float4*)x, (const float4*)Wq, (const float4*)Wk,
        (const float4*)Wv, (const float4*)Wo,
        (uint2*)xh, (uint2*)xl, (uint2*)wqh, (uint2*)wql,
        (uint2*)wkh, (uint2*)wkl, (uint2*)wvh, (uint2*)wvl,
        (uint2*)woh, (uint2*)wol);

    // Fused QKV projection: q,k -> fp32 g_qkv; v -> split bf16 directly
    gemm_b16<true><<<dim3(32, 32), 256, GEMM_DSMEM>>>(
        xh, xl, wqh, wql, wkh, wkl, wvh, wvl, qkv, vh, vl, 4096, HID_D);

    // RoPE + scale + split (q,k)
    {
        int total = S_LEN * (NH_Q + N_KV) * 128;
        rope_split_qk<<<(total + 255) / 256, 256>>>(qkv, pos, qh, ql, kh2, kl2);
    }

    // Flash attention (HMMA, 512 threads, split bf16 in/out)
    attn_mma<<<dim3(S_LEN / 64, NH_Q), 512, ATTN_SMEM_BYTES>>>(
        qh, ql, kh2, kl2, vh, vl, aoh, aol);

    // Output projection
    gemm_b16<false><<<dim3(18, 32), 256, GEMM_DSMEM>>>(
        aoh, aol, woh, wol, woh, wol, woh, wol, out, nullptr, nullptr, HID_D, QO_W);
}

// round 16
// speedup vs baseline: 1.0759x; 1.0759x over previous
#include <cuda_runtime.h>
#include <cuda_bf16.h>
#include <math.h>
#include <stdint.h>

// Problem constants
#define S_LEN 4096
#define HID_D 2304
#define NH_Q 8
#define N_KV 4
#define HD_H 256
#define SWIN 2048
#define QO_W (NH_Q * HD_H)   // 2048
#define KV_W (N_KV * HD_H)   // 1024

// fused QKV fp32 output: cols [0,2048)=q, [2048,3072)=k  (v goes direct to bf16)
__device__ float g_qkv[S_LEN * 4096];
// split bf16 operands
__device__ __nv_bfloat16 g_xh [S_LEN * HID_D],  g_xl [S_LEN * HID_D];
__device__ __nv_bfloat16 g_wqh[QO_W * HID_D],   g_wql[QO_W * HID_D];
__device__ __nv_bfloat16 g_wkh[KV_W * HID_D],   g_wkl[KV_W * HID_D];
__device__ __nv_bfloat16 g_wvh[KV_W * HID_D],   g_wvl[KV_W * HID_D];
__device__ __nv_bfloat16 g_woh[HID_D * QO_W],   g_wol[HID_D * QO_W];
__device__ __nv_bfloat16 g_qh [S_LEN * QO_W],   g_ql [S_LEN * QO_W];
__device__ __nv_bfloat16 g_kh [S_LEN * KV_W],   g_kl [S_LEN * KV_W];
__device__ __nv_bfloat16 g_vh [S_LEN * KV_W],   g_vl [S_LEN * KV_W];
__device__ __nv_bfloat16 g_aoh[S_LEN * QO_W],   g_aol[S_LEN * QO_W];

// ===========================================================================
// helpers
// ===========================================================================
__device__ __forceinline__ uint32_t smem_u32(const void* p) {
    uint32_t a;
    asm("{ .reg .u64 t; cvta.to.shared.u64 t, %1; cvt.u32.u64 %0, t; }" : "=r"(a) : "l"(p));
    return a;
}

__device__ __forceinline__ uint32_t pack_bf16_rn(float lo, float hi) {
    uint32_t r;
    asm("cvt.rn.bf16x2.f32 %0, %1, %2;" : "=r"(r) : "f"(hi), "f"(lo));
    return r;
}

__device__ __forceinline__ void split4(float4 v, uint32_t& h0, uint32_t& h1,
                                       uint32_t& l0, uint32_t& l1) {
    uint32_t bx = __float_as_uint(v.x), by = __float_as_uint(v.y);
    uint32_t bz = __float_as_uint(v.z), bw = __float_as_uint(v.w);
    h0 = __byte_perm(bx, by, 0x7632);
    h1 = __byte_perm(bz, bw, 0x7632);
    float lx = v.x - __uint_as_float(bx & 0xFFFF0000u);
    float ly = v.y - __uint_as_float(by & 0xFFFF0000u);
    float lz = v.z - __uint_as_float(bz & 0xFFFF0000u);
    float lw = v.w - __uint_as_float(bw & 0xFFFF0000u);
    l0 = pack_bf16_rn(lx, ly);
    l1 = pack_bf16_rn(lz, lw);
}

__device__ __forceinline__ void split2(float a, float b, uint32_t& uh, uint32_t& ul) {
    uint32_t ba = __float_as_uint(a), bb = __float_as_uint(b);
    uh = __byte_perm(ba, bb, 0x7632);
    float ra = a - __uint_as_float(ba & 0xFFFF0000u);
    float rb = b - __uint_as_float(bb & 0xFFFF0000u);
    ul = pack_bf16_rn(ra, rb);
}

#define LDSM4(R0, R1, R2, R3, ADDR) \
    asm volatile("ldmatrix.sync.aligned.m8n8.x4.shared.b16 {%0,%1,%2,%3}, [%4];" \
        : "=r"(R0), "=r"(R1), "=r"(R2), "=r"(R3) : "r"(ADDR))

#define LDSM4T(R0, R1, R2, R3, ADDR) \
    asm volatile("ldmatrix.sync.aligned.m8n8.x4.trans.shared.b16 {%0,%1,%2,%3}, [%4];" \
        : "=r"(R0), "=r"(R1), "=r"(R2), "=r"(R3) : "r"(ADDR))

#define MMA16816(CC, A0, A1, A2, A3, B0, B1) \
    asm volatile("mma.sync.aligned.m16n8k16.row.col.f32.bf16.bf16.f32 " \
        "{%0,%1,%2,%3}, {%4,%5,%6,%7}, {%8,%9}, {%0,%1,%2,%3};" \
        : "+f"((CC)[0]), "+f"((CC)[1]), "+f"((CC)[2]), "+f"((CC)[3]) \
        : "r"(A0), "r"(A1), "r"(A2), "r"(A3), "r"(B0), "r"(B1))

#define CPA16(DST, SRC) \
    asm volatile("cp.async.ca.shared.global [%0], [%1], 16;" :: "r"(DST), "l"(SRC) : "memory")
#define CPA_COMMIT() asm volatile("cp.async.commit_group;" ::: "memory")
template<int NN> __device__ __forceinline__ void cpa_wait() {
    asm volatile("cp.async.wait_group %0;" :: "n"(NN) : "memory");
}

#define STS128(ADDR, V) \
    asm volatile("st.shared.v4.b32 [%0], {%1,%2,%3,%4};" \
        :: "r"(ADDR), "r"((V).x), "r"((V).y), "r"((V).z), "r"((V).w) : "memory")
#define STS32(ADDR, V) \
    asm volatile("st.shared.b32 [%0], %1;" :: "r"(ADDR), "r"(V) : "memory")

// ===========================================================================
// fused split kernel: all 5 fp32 inputs -> bf16 hi/lo arrays in ONE launch
// ===========================================================================
#define SEG0 2359296                // x:  4096*2304/4
#define SEG1 (SEG0 + 1179648)       // wq: 2048*2304/4
#define SEG2 (SEG1 + 589824)        // wk: 1024*2304/4
#define SEG3 (SEG2 + 589824)        // wv
#define SEG4 (SEG3 + 1179648)       // wo: 2304*2048/4

__global__ void split_all(
    const float4* __restrict__ x,  const float4* __restrict__ wq,
    const float4* __restrict__ wk, const float4* __restrict__ wv,
    const float4* __restrict__ wo,
    uint2* xh, uint2* xl, uint2* qh, uint2* ql, uint2* kh, uint2* kl,
    uint2* vh, uint2* vl, uint2* oh, uint2* ol)
{
    int i = blockIdx.x * blockDim.x + threadIdx.x;
    if (i >= SEG4) return;
    const float4* s; uint2 *h, *l; int j;
    if (i < SEG0)      { s = x;  h = xh; l = xl; j = i; }
    else if (i < SEG1) { s = wq; h = qh; l = ql; j = i - SEG0; }
    else if (i < SEG2) { s = wk; h = kh; l = kl; j = i - SEG1; }
    else if (i < SEG3) { s = wv; h = vh; l = vl; j = i - SEG2; }
    else               { s = wo; h = oh; l = ol; j = i - SEG3; }
    float4 v = s[j];
    uint32_t h0, h1, l0, l1;
    split4(v, h0, h1, l0, l1);
    h[j] = make_uint2(h0, h1);
    l[j] = make_uint2(l0, l1);
}

// ===========================================================================
// HMMA GEMM (unchanged from R13): 128x128 CTA, BK=64, cp.async 3-stage ring,
// GROUP_M=8 swizzle; QKV segment-select with direct split-v epilogue.
// ===========================================================================
#define GSTAGE  65536
#define GOFF_AL 16384
#define GOFF_BH 32768
#define GOFF_BL 49152

template<bool QKV>
__global__ void __launch_bounds__(256) gemm_b16(
    const __nv_bfloat16* __restrict__ Ah, const __nv_bfloat16* __restrict__ Al,
    const __nv_bfloat16* __restrict__ B0h, const __nv_bfloat16* __restrict__ B0l,
    const __nv_bfloat16* __restrict__ B1h, const __nv_bfloat16* __restrict__ B1l,
    const __nv_bfloat16* __restrict__ B2h, const __nv_bfloat16* __restrict__ B2l,
    float* __restrict__ C, __nv_bfloat16* __restrict__ Ch, __nv_bfloat16* __restrict__ Cl,
    int N, int K)
{
    extern __shared__ unsigned char dsm[];
    uint32_t sb = smem_u32(dsm);
    sb = (sb + 1023u) & ~1023u;

    const int tid  = threadIdx.x;
    const int wid  = tid >> 5;
    const int lane = tid & 31;
    const int wm   = (wid >> 2) * 64;
    const int wn   = (wid & 3) * 32;

    int m0, n0;
    {
        const int nbx = gridDim.x, nby = gridDim.y;
        int pid = blockIdx.y * nbx + blockIdx.x;
        int group = 8 * nbx;
        int gid = pid / group;
        int first_m = gid * 8;
        int gsz = nby - first_m; if (gsz > 8) gsz = 8;
        m0 = (first_m + (pid % group) % gsz) * 128;
        n0 = ((pid % group) / gsz) * 128;
    }
    const int NI = K >> 6;

    const __nv_bfloat16 *Bh, *Bl;
    int nb;
    if (!QKV || n0 < 2048)      { Bh = B0h; Bl = B0l; nb = n0; }
    else if (n0 < 3072)         { Bh = B1h; Bl = B1l; nb = n0 - 2048; }
    else                        { Bh = B2h; Bl = B2l; nb = n0 - 3072; }

    float acc[4][4][4];
#pragma unroll
    for (int mt = 0; mt < 4; mt++)
#pragma unroll
        for (int nt = 0; nt < 4; nt++)
#pragma unroll
            for (int q = 0; q < 4; q++) acc[mt][nt][q] = 0.f;

    const int a_r = (lane & 7) + ((lane >> 3) & 1) * 8;
    const int a_c = (lane >> 4) & 1;
    const int b_r = (lane & 7) + ((lane >> 4) & 1) * 8;
    const int b_c = (lane >> 3) & 1;

    int cr[4], cc[4];
    uint32_t cof[4];
#pragma unroll
    for (int k = 0; k < 4; k++) {
        int idx = tid + k * 256;
        cr[k] = idx >> 3; cc[k] = idx & 7;
        cof[k] = cr[k] * 128 + ((cc[k] ^ (cr[k] & 7)) << 4);
    }

    auto issue = [&](int k0, uint32_t base) {
        const char* pAh = (const char*)Ah + ((size_t)m0 * K + k0) * 2;
        const char* pAl = (const char*)Al + ((size_t)m0 * K + k0) * 2;
        const char* pBh = (const char*)Bh + ((size_t)nb * K + k0) * 2;
        const char* pBl = (const char*)Bl + ((size_t)nb * K + k0) * 2;
#pragma unroll
        for (int k = 0; k < 4; k++) {
            size_t so = (size_t)cr[k] * K * 2 + cc[k] * 16;
            CPA16(base + cof[k],           pAh + so);
            CPA16(base + GOFF_AL + cof[k], pAl + so);
            CPA16(base + GOFF_BH + cof[k], pBh + so);
            CPA16(base + GOFF_BL + cof[k], pBl + so);
        }
        CPA_COMMIT();
    };

    issue(0, sb);
    issue(64, sb + GSTAGE);

    int st = 0;
    for (int it = 0; it < NI; it++) {
        if (it + 1 < NI) cpa_wait<1>(); else cpa_wait<0>();
        __syncthreads();
        if (it + 2 < NI) {
            int st2 = st + 2; if (st2 >= 3) st2 -= 3;
            issue((it + 2) * 64, sb + st2 * GSTAGE);
        }
        const uint32_t sAh = sb + st * GSTAGE;
        const uint32_t sAl = sAh + GOFF_AL;
        const uint32_t sBh = sAh + GOFF_BH;
        const uint32_t sBl = sAh + GOFF_BL;

#pragma unroll
        for (int ks = 0; ks < 4; ks++) {
            const int cb = ks * 2;
            uint32_t ah[4][4], bh[4][2], bl[4][2];

#pragma unroll
            for (int mt = 0; mt < 4; mt++) {
                int r = wm + mt * 16 + a_r;
                uint32_t ad = sAh + r * 128 + (((cb + a_c) ^ (r & 7)) << 4);
                LDSM4(ah[mt][0], ah[mt][1], ah[mt][2], ah[mt][3], ad);
            }
#pragma unroll
            for (int np = 0; np < 2; np++) {
                int r = wn + np * 16 + b_r;
                uint32_t bd = sBh + r * 128 + (((cb + b_c) ^ (r & 7)) << 4);
                LDSM4(bh[2 * np][0], bh[2 * np][1], bh[2 * np + 1][0], bh[2 * np + 1][1], bd);
            }
#pragma unroll
            for (int mt = 0; mt < 4; mt++)
#pragma unroll
                for (int nt = 0; nt < 4; nt++)
                    MMA16816(acc[mt][nt], ah[mt][0], ah[mt][1], ah[mt][2], ah[mt][3],
                             bh[nt][0], bh[nt][1]);
#pragma unroll
            for (int np = 0; np < 2; np++) {
                int r = wn + np * 16 + b_r;
                uint32_t bd = sBl + r * 128 + (((cb + b_c) ^ (r & 7)) << 4);
                LDSM4(bl[2 * np][0], bl[2 * np][1], bl[2 * np + 1][0], bl[2 * np + 1][1], bd);
            }
#pragma unroll
            for (int mt = 0; mt < 4; mt++)
#pragma unroll
                for (int nt = 0; nt < 4; nt++)
                    MMA16816(acc[mt][nt], ah[mt][0], ah[mt][1], ah[mt][2], ah[mt][3],
                             bl[nt][0], bl[nt][1]);
#pragma unroll
            for (int mt = 0; mt < 4; mt++) {
                int r = wm + mt * 16 + a_r;
                uint32_t ad = sAl + r * 128 + (((cb + a_c) ^ (r & 7)) << 4);
                LDSM4(ah[mt][0], ah[mt][1], ah[mt][2], ah[mt][3], ad);
            }
#pragma unroll
            for (int mt = 0; mt < 4; mt++)
#pragma unroll
                for (int nt = 0; nt < 4; nt++)
                    MMA16816(acc[mt][nt], ah[mt][0], ah[mt][1], ah[mt][2], ah[mt][3],
                             bh[nt][0], bh[nt][1]);
        }
        if (++st >= 3) st -= 3;
    }

    const int lr = lane >> 2;
    const int lc = (lane & 3) * 2;
    if (QKV && n0 >= 3072) {
#pragma unroll
        for (int mt = 0; mt < 4; mt++) {
#pragma unroll
            for (int nt = 0; nt < 4; nt++) {
                size_t idx = (size_t)(m0 + wm + mt * 16 + lr) * KV_W +
                             (n0 - 3072) + wn + nt * 8 + lc;
                uint32_t uh, ul;
                split2(acc[mt][nt][0], acc[mt][nt][1], uh, ul);
                *(uint32_t*)(Ch + idx) = uh;
                *(uint32_t*)(Cl + idx) = ul;
                split2(acc[mt][nt][2], acc[mt][nt][3], uh, ul);
                *(uint32_t*)(Ch + idx + 8 * (size_t)KV_W) = uh;
                *(uint32_t*)(Cl + idx + 8 * (size_t)KV_W) = ul;
            }
        }
    } else {
#pragma unroll
        for (int mt = 0; mt < 4; mt++) {
#pragma unroll
            for (int nt = 0; nt < 4; nt++) {
                float* p = C + (size_t)(m0 + wm + mt * 16 + lr) * N + n0 + wn + nt * 8 + lc;
                *(float2*)p           = make_float2(acc[mt][nt][0], acc[mt][nt][1]);
                *(float2*)(p + 8 * N) = make_float2(acc[mt][nt][2], acc[mt][nt][3]);
            }
        }
    }
}

// ---------------------------------------------------------------------------
// Post-QKV: rope+split for q,k (unchanged from R13).
// ---------------------------------------------------------------------------
__global__ void rope_split_qk(const float* __restrict__ qkv, const int* __restrict__ pos,
                              __nv_bfloat16* __restrict__ qh, __nv_bfloat16* __restrict__ ql,
                              __nv_bfloat16* __restrict__ kh, __nv_bfloat16* __restrict__ kl)
{
    const int TQ = S_LEN * NH_Q * 128;
    const int TK = S_LEN * N_KV * 128;
    int i = blockIdx.x * blockDim.x + threadIdx.x;
    if (i >= TQ + TK) return;

    const float* src;
    __nv_bfloat16 *bh, *bl;
    int s, d;
    float scale;
    if (i < TQ) {
        d = i & 127;
        int hh = (i >> 7) & 7;
        s = i >> 10;
        src = qkv + (size_t)s * 4096 + hh * HD_H;
        bh = qh + (size_t)s * QO_W + hh * HD_H;
        bl = ql + (size_t)s * QO_W + hh * HD_H;
        scale = 0.0625f;
    } else {
        int j = i - TQ;
        d = j & 127;
        int hh = (j >> 7) & 3;
        s = j >> 9;
        src = qkv + (size_t)s * 4096 + 2048 + hh * HD_H;
        bh = kh + (size_t)s * KV_W + hh * HD_H;
        bl = kl + (size_t)s * KV_W + hh * HD_H;
        scale = 1.f;
    }
    float p   = (float)pos[s];
    float inv = powf(10000.f, -(float)d * (1.f / 128.f));
    float ang = p * inv;
    float c, sn;
    sincosf(ang, &sn, &c);
    float x1 = src[d];
    float x2 = src[d + 128];
    float y1 = (x1 * c - x2 * sn) * scale;
    float y2 = (x2 * c + x1 * sn) * scale;

    uint32_t b1 = __float_as_uint(y1), b2 = __float_as_uint(y2);
    *(uint16_t*)(bh + d)       = (uint16_t)(b1 >> 16);
    *(uint16_t*)(bh + d + 128) = (uint16_t)(b2 >> 16);
    bl[d]       = __float2bfloat16(y1 - __uint_as_float(b1 & 0xFFFF0000u));
    bl[d + 128] = __float2bfloat16(y2 - __uint_as_float(b2 & 0xFFFF0000u));
}

// ===========================================================================
// Flash attention on HMMA, R13 config (256 threads) with FIXED-MAX softmax:
// softcap bounds scores <= 50, so exp(s-50) replaces the running max.
// No fp32 Ps array, no max passes, no O rescale. Register exp -> P hi/lo
// stores; row sums via 4-lane shuffle + 2-entry smem combine.
// ===========================================================================
#define AOFF_QH  0
#define AOFF_QL  32768
#define AOFF_VH  65536
#define AOFF_VL  98304
#define AOFF_KH  131072    // 8192
#define AOFF_KL  139264    // 8192
#define AOFF_PBH 147456    // 8192
#define AOFF_PBL 155648    // 8192
#define AOFF_LS  163840    // 256
#define AOFF_RED 164096    // 512
#define ATTN_SMEM_BYTES (164608 + 128)

__global__ void __launch_bounds__(256) attn_mma(
    const __nv_bfloat16* __restrict__ qh, const __nv_bfloat16* __restrict__ ql,
    const __nv_bfloat16* __restrict__ kh, const __nv_bfloat16* __restrict__ kl,
    const __nv_bfloat16* __restrict__ vh, const __nv_bfloat16* __restrict__ vl,
    __nv_bfloat16* __restrict__ aoh, __nv_bfloat16* __restrict__ aol)
{
    extern __shared__ unsigned char asm_raw[];
    uint32_t sb = smem_u32(asm_raw);
    sb = (sb + 127u) & ~127u;
    const uint32_t pad = sb - smem_u32(asm_raw);

    const uint32_t sQh = sb + AOFF_QH,  sQl = sb + AOFF_QL;
    const uint32_t sVh = sb + AOFF_VH,  sVl = sb + AOFF_VL;
    const uint32_t sKh = sb + AOFF_KH,  sKl = sb + AOFF_KL;
    const uint32_t sPh = sb + AOFF_PBH, sPl = sb + AOFF_PBL;
    float* l_s = (float*)(asm_raw + pad + AOFF_LS);
    float* red = (float*)(asm_raw + pad + AOFF_RED);

    const int tid  = threadIdx.x;
    const int wid  = tid >> 5;
    const int lane = tid & 31;
    const int wr   = wid >> 1;
    const int wc   = wid & 1;
    const int qt   = gridDim.x - 1 - blockIdx.x;
    const int h    = blockIdx.y;
    const int qs   = qt * 64;
    const int kvh  = h >> 1;
    const float CAP = 50.f, INV_CAP2 = 2.f / 50.f;

    const int a_r = (lane & 7) + ((lane >> 3) & 1) * 8;
    const int a_c = (lane >> 4) & 1;
    const int b_r = (lane & 7) + ((lane >> 4) & 1) * 8;
    const int b_c = (lane >> 3) & 1;
    const int lr  = lane >> 2;
    const int lc  = (lane & 3) * 2;
    const int l4  = lane & 3;

    // ---- load pre-split Q (64 x 256 bf16, already scaled) ----
    {
        const char* qhb = (const char*)(qh + (size_t)qs * QO_W + h * HD_H);
        const char* qlb = (const char*)(ql + (size_t)qs * QO_W + h * HD_H);
#pragma unroll
        for (int i = 0; i < 8; i++) {
            int idx = tid + i * 256;
            int r = idx >> 5, c = idx & 31;
            uint32_t off = r * 512 + ((c ^ (r & 7)) << 4);
            uint4 vh4 = *(const uint4*)(qhb + (size_t)r * QO_W * 2 + c * 16);
            uint4 vl4 = *(const uint4*)(qlb + (size_t)r * QO_W * 2 + c * 16);
            STS128(sQh + off, vh4);
            STS128(sQl + off, vl4);
        }
    }
    if (tid < 64) l_s[tid] = 0.f;

    float o[16][4];
#pragma unroll
    for (int nt = 0; nt < 16; nt++)
#pragma unroll
        for (int q = 0; q < 4; q++) o[nt][q] = 0.f;

    const int kt_lo = (qs - (SWIN - 1) > 0 ? qs - (SWIN - 1) : 0) >> 6;
    const __nv_bfloat16* khb0 = kh + kvh * HD_H;
    const __nv_bfloat16* klb0 = kl + kvh * HD_H;
    const __nv_bfloat16* vhb0 = vh + kvh * HD_H;
    const __nv_bfloat16* vlb0 = vl + kvh * HD_H;

    const int s_r = tid >> 3, s_c = tid & 7;
    const int s_r1 = (tid + 256) >> 3, s_c1 = (tid + 256) & 7;
    uint4 stKh[2], stKl[2], stVh[2], stVl[2];

    for (int kt = qt; kt >= kt_lo; kt--) {
        const int ks0 = kt * 64;
        const char* khr = (const char*)(khb0 + (size_t)ks0 * KV_W);
        const char* klr = (const char*)(klb0 + (size_t)ks0 * KV_W);
        const char* vhr = (const char*)(vhb0 + (size_t)ks0 * KV_W);
        const char* vlr = (const char*)(vlb0 + (size_t)ks0 * KV_W);

        auto stage = [&](int dc) {
            size_t o0 = (size_t)s_r * KV_W * 2 + dc * 128 + s_c * 16;
            size_t o1 = (size_t)s_r1 * KV_W * 2 + dc * 128 + s_c1 * 16;
            stKh[0] = *(const uint4*)(khr + o0);  stKh[1] = *(const uint4*)(khr + o1);
            stKl[0] = *(const uint4*)(klr + o0);  stKl[1] = *(const uint4*)(klr + o1);
            stVh[0] = *(const uint4*)(vhr + o0);  stVh[1] = *(const uint4*)(vhr + o1);
            stVl[0] = *(const uint4*)(vlr + o0);  stVl[1] = *(const uint4*)(vlr + o1);
        };

        float s[4][4];
#pragma unroll
        for (int nt = 0; nt < 4; nt++)
#pragma unroll
            for (int q = 0; q < 4; q++) s[nt][q] = 0.f;

        stage(0);

        for (int dc = 0; dc < 4; dc++) {
            __syncthreads();
            {
                uint32_t offk0 = s_r * 128 + ((s_c ^ (s_r & 7)) << 4);
                uint32_t offk1 = s_r1 * 128 + ((s_c1 ^ (s_r1 & 7)) << 4);
                uint32_t offv0 = s_r * 512 + (((dc * 8 + s_c) ^ (s_r & 7)) << 4);
                uint32_t offv1 = s_r1 * 512 + (((dc * 8 + s_c1) ^ (s_r1 & 7)) << 4);
                STS128(sKh + offk0, stKh[0]);  STS128(sKh + offk1, stKh[1]);
                STS128(sKl + offk0, stKl[0]);  STS128(sKl + offk1, stKl[1]);
                STS128(sVh + offv0, stVh[0]);  STS128(sVh + offv1, stVh[1]);
                STS128(sVl + offv0, stVl[0]);  STS128(sVl + offv1, stVl[1]);
            }
            __syncthreads();
            if (dc < 3) stage(dc + 1);

#pragma unroll
            for (int ks = 0; ks < 4; ks++) {
                const int cbq = dc * 8 + ks * 2;
                const int cbk = ks * 2;
                uint32_t ah[4], al[4], bh[2][4], bl[4];
                {
                    int r = wr * 16 + a_r;
                    LDSM4(ah[0], ah[1], ah[2], ah[3],
                          sQh + r * 512 + (((cbq + a_c) ^ (r & 7)) << 4));
                    LDSM4(al[0], al[1], al[2], al[3],
                          sQl + r * 512 + (((cbq + a_c) ^ (r & 7)) << 4));
                }
#pragma unroll
                for (int np = 0; np < 2; np++) {
                    int r = wc * 32 + np * 16 + b_r;
                    LDSM4(bh[np][0], bh[np][1], bh[np][2], bh[np][3],
                          sKh + r * 128 + (((cbk + b_c) ^ (r & 7)) << 4));
                }
#pragma unroll
                for (int np = 0; np < 2; np++) {
                    MMA16816(s[2 * np],     ah[0], ah[1], ah[2], ah[3], bh[np][0], bh[np][1]);
                    MMA16816(s[2 * np + 1], ah[0], ah[1], ah[2], ah[3], bh[np][2], bh[np][3]);
                    MMA16816(s[2 * np],     al[0], al[1], al[2], al[3], bh[np][0], bh[np][1]);
                    MMA16816(s[2 * np + 1], al[0], al[1], al[2], al[3], bh[np][2], bh[np][3]);
                }
#pragma unroll
                for (int np = 0; np < 2; np++) {
                    int r = wc * 32 + np * 16 + b_r;
                    LDSM4(bl[0], bl[1], bl[2], bl[3],
                          sKl + r * 128 + (((cbk + b_c) ^ (r & 7)) << 4));
                    MMA16816(s[2 * np],     ah[0], ah[1], ah[2], ah[3], bl[0], bl[1]);
                    MMA16816(s[2 * np + 1], ah[0], ah[1], ah[2], ah[3], bl[2], bl[3]);
                }
            }
        }

        // ---- fixed-max softmax in regs: e = exp(softcap(s) - CAP) ----
        //      softcap(s) - CAP = -2*CAP / (exp(s*2/CAP) + 1)
        {
            float sums[2] = {0.f, 0.f};
#pragma unroll
            for (int nt = 0; nt < 4; nt++) {
                int col = wc * 32 + nt * 8 + lc;
                int gj0 = ks0 + col;
#pragma unroll
                for (int half = 0; half < 2; half++) {
                    int row = wr * 16 + lr + half * 8;
                    int gi = qs + row;
                    float t0 = __expf(s[nt][2 * half + 0] * INV_CAP2);
                    float t1 = __expf(s[nt][2 * half + 1] * INV_CAP2);
                    float e0 = __expf(-__fdividef(2.f * CAP, t0 + 1.f));
                    float e1 = __expf(-__fdividef(2.f * CAP, t1 + 1.f));
                    bool ok0 = (gj0 <= gi)     && ((gi - gj0) < SWIN);
                    bool ok1 = (gj0 + 1 <= gi) && ((gi - gj0 - 1) < SWIN);
                    e0 = ok0 ? e0 : 0.f;
                    e1 = ok1 ? e1 : 0.f;
                    sums[half] += e0 + e1;
                    uint32_t ph, pl;
                    split2(e0, e1, ph, pl);
                    uint32_t off = row * 128 +
                        ((((uint32_t)(wc * 4 + nt)) ^ (row & 7)) << 4) + lc * 2;
                    STS32(sPh + off, ph);
                    STS32(sPl + off, pl);
                }
            }
#pragma unroll
            for (int mk = 1; mk <= 2; mk <<= 1) {
                sums[0] += __shfl_xor_sync(0xFFFFFFFFu, sums[0], mk);
                sums[1] += __shfl_xor_sync(0xFFFFFFFFu, sums[1], mk);
            }
            if (l4 == 0) {
                red[(wr * 16 + lr) * 2 + wc]     = sums[0];
                red[(wr * 16 + lr + 8) * 2 + wc] = sums[1];
            }
        }
        __syncthreads();   // P stores + red visible
        if (tid < 64) l_s[tid] += red[tid * 2] + red[tid * 2 + 1];

        // ---- O += P V (3-term: Ph*Vh + Ph*Vl + Pl*Vh) ----
#pragma unroll
        for (int kk = 0; kk < 4; kk++) {
            uint32_t ah[4], al[4];
            {
                int r = wr * 16 + a_r;
                uint32_t c = kk * 2 + a_c;
                LDSM4(ah[0], ah[1], ah[2], ah[3], sPh + r * 128 + ((c ^ (r & 7)) << 4));
                LDSM4(al[0], al[1], al[2], al[3], sPl + r * 128 + ((c ^ (r & 7)) << 4));
            }
#pragma unroll
            for (int vp = 0; vp < 8; vp++) {
                int key = kk * 16 + a_r;
                uint32_t chv = wc * 16 + vp * 2 + a_c;
                uint32_t vb[4], vl4[4];
                LDSM4T(vb[0], vb[1], vb[2], vb[3],
                       sVh + key * 512 + ((chv ^ (key & 7)) << 4));
                MMA16816(o[2 * vp],     ah[0], ah[1], ah[2], ah[3], vb[0], vb[1]);
                MMA16816(o[2 * vp + 1], ah[0], ah[1], ah[2], ah[3], vb[2], vb[3]);
                MMA16816(o[2 * vp],     al[0], al[1], al[2], al[3], vb[0], vb[1]);
                MMA16816(o[2 * vp + 1], al[0], al[1], al[2], al[3], vb[2], vb[3]);
                LDSM4T(vl4[0], vl4[1], vl4[2], vl4[3],
                       sVl + key * 512 + ((chv ^ (key & 7)) << 4));
                MMA16816(o[2 * vp],     ah[0], ah[1], ah[2], ah[3], vl4[0], vl4[1]);
                MMA16816(o[2 * vp + 1], ah[0], ah[1], ah[2], ah[3], vl4[2], vl4[3]);
            }
        }
    }

    __syncthreads();
    // ---- normalize + split + write bf16 ----
    {
        float inva = 1.f / l_s[wr * 16 + lr];
        float invb = 1.f / l_s[wr * 16 + lr + 8];
        size_t i0 = (size_t)(qs + wr * 16 + lr) * QO_W + h * HD_H + wc * 128;
        size_t i1 = i0 + 8 * (size_t)QO_W;
#pragma unroll
        for (int nt = 0; nt < 16; nt++) {
            uint32_t uh, ul;
            split2(o[nt][0] * inva, o[nt][1] * inva, uh, ul);
            *(uint32_t*)(aoh + i0 + nt * 8 + lc) = uh;
            *(uint32_t*)(aol + i0 + nt * 8 + lc) = ul;
            split2(o[nt][2] * invb, o[nt][3] * invb, uh, ul);
            *(uint32_t*)(aoh + i1 + nt * 8 + lc) = uh;
            *(uint32_t*)(aol + i1 + nt * 8 + lc) = ul;
        }
    }
}

// ---------------------------------------------------------------------------
// Launch
// ---------------------------------------------------------------------------
#define GEMM_DSMEM (3 * GSTAGE + 1024)

extern "C" void kernel_launch(void* const* d_in, const int* in_sizes, int n_in,
                              void* d_out, int out_size)
{
    const float* x   = (const float*)d_in[0];   // [4096, 2304]
    const int*   pos = (const int*)  d_in[1];   // [1, 4096]
    const float* Wq  = (const float*)d_in[2];   // [2048, 2304]
    const float* Wk  = (const float*)d_in[3];   // [1024, 2304]
    const float* Wv  = (const float*)d_in[4];   // [1024, 2304]
    const float* Wo  = (const float*)d_in[5];   // [2304, 2048]
    float* out = (float*)d_out;                 // [4096, 2304]

    float* qkv;
    __nv_bfloat16 *xh, *xl, *wqh, *wql, *wkh, *wkl, *wvh, *wvl, *woh, *wol;
    __nv_bfloat16 *qh, *ql, *kh2, *kl2, *vh, *vl, *aoh, *aol;
    cudaGetSymbolAddress((void**)&qkv, g_qkv);
    cudaGetSymbolAddress((void**)&xh,  g_xh);  cudaGetSymbolAddress((void**)&xl,  g_xl);
    cudaGetSymbolAddress((void**)&wqh, g_wqh); cudaGetSymbolAddress((void**)&wql, g_wql);
    cudaGetSymbolAddress((void**)&wkh, g_wkh); cudaGetSymbolAddress((void**)&wkl, g_wkl);
    cudaGetSymbolAddress((void**)&wvh, g_wvh); cudaGetSymbolAddress((void**)&wvl, g_wvl);
    cudaGetSymbolAddress((void**)&woh, g_woh); cudaGetSymbolAddress((void**)&wol, g_wol);
    cudaGetSymbolAddress((void**)&qh,  g_qh);  cudaGetSymbolAddress((void**)&ql,  g_ql);
    cudaGetSymbolAddress((void**)&kh2, g_kh);  cudaGetSymbolAddress((void**)&kl2, g_kl);
    cudaGetSymbolAddress((void**)&vh,  g_vh);  cudaGetSymbolAddress((void**)&vl,  g_vl);
    cudaGetSymbolAddress((void**)&aoh, g_aoh); cudaGetSymbolAddress((void**)&aol, g_aol);

    cudaFuncSetAttribute(gemm_b16<true>,  cudaFuncAttributeMaxDynamicSharedMemorySize, GEMM_DSMEM);
    cudaFuncSetAttribute(gemm_b16<false>, cudaFuncAttributeMaxDynamicSharedMemorySize, GEMM_DSMEM);
    cudaFuncSetAttribute(attn_mma, cudaFuncAttributeMaxDynamicSharedMemorySize, ATTN_SMEM_BYTES);

    // One fused split of all fp32 inputs
    split_all<<<(SEG4 + 255) / 256, 256>>>(
        (const float4*)x, (const float4*)Wq, (const float4*)Wk,
        (const float4*)Wv, (const float4*)Wo,
        (uint2*)xh, (uint2*)xl, (uint2*)wqh, (uint2*)wql,
        (uint2*)wkh, (uint2*)wkl, (uint2*)wvh, (uint2*)wvl,
        (uint2*)woh, (uint2*)wol);

    // Fused QKV projection: q,k -> fp32 g_qkv; v -> split bf16 directly
    gemm_b16<true><<<dim3(32, 32), 256, GEMM_DSMEM>>>(
        xh, xl, wqh, wql, wkh, wkl, wvh, wvl, qkv, vh, vl, 4096, HID_D);

    // RoPE + scale + split (q,k)
    {
        int total = S_LEN * (NH_Q + N_KV) * 128;
        rope_split_qk<<<(total + 255) / 256, 256>>>(qkv, pos, qh, ql, kh2, kl2);
    }

    // Flash attention (HMMA, fixed-max softmax, split bf16 in/out)
    attn_mma<<<dim3(S_LEN / 64, NH_Q), 256, ATTN_SMEM_BYTES>>>(
        qh, ql, kh2, kl2, vh, vl, aoh, aol);

    // Output projection
    gemm_b16<false><<<dim3(18, 32), 256, GEMM_DSMEM>>>(
        aoh, aol, woh, wol, woh, wol, woh, wol, out, nullptr, nullptr, HID_D, QO_W);
}

// round 17
// speedup vs baseline: 1.1013x; 1.0236x over previous
#include <cuda_runtime.h>
#include <cuda_bf16.h>
#include <math.h>
#include <stdint.h>

// Problem constants
#define S_LEN 4096
#define HID_D 2304
#define NH_Q 8
#define N_KV 4
#define HD_H 256
#define SWIN 2048
#define QO_W (NH_Q * HD_H)   // 2048
#define KV_W (N_KV * HD_H)   // 1024

// fused QKV fp32 output: cols [0,2048)=q, [2048,3072)=k  (v goes direct to bf16)
__device__ float g_qkv[S_LEN * 4096];
// split bf16 operands
__device__ __nv_bfloat16 g_xh [S_LEN * HID_D],  g_xl [S_LEN * HID_D];
__device__ __nv_bfloat16 g_wqh[QO_W * HID_D],   g_wql[QO_W * HID_D];
__device__ __nv_bfloat16 g_wkh[KV_W * HID_D],   g_wkl[KV_W * HID_D];
__device__ __nv_bfloat16 g_wvh[KV_W * HID_D],   g_wvl[KV_W * HID_D];
__device__ __nv_bfloat16 g_woh[HID_D * QO_W],   g_wol[HID_D * QO_W];
__device__ __nv_bfloat16 g_qh [S_LEN * QO_W],   g_ql [S_LEN * QO_W];
__device__ __nv_bfloat16 g_kh [S_LEN * KV_W],   g_kl [S_LEN * KV_W];
__device__ __nv_bfloat16 g_vh [S_LEN * KV_W],   g_vl [S_LEN * KV_W];
__device__ __nv_bfloat16 g_aoh[S_LEN * QO_W],   g_aol[S_LEN * QO_W];

// ===========================================================================
// helpers
// ===========================================================================
__device__ __forceinline__ uint32_t smem_u32(const void* p) {
    uint32_t a;
    asm("{ .reg .u64 t; cvta.to.shared.u64 t, %1; cvt.u32.u64 %0, t; }" : "=r"(a) : "l"(p));
    return a;
}

__device__ __forceinline__ uint32_t pack_bf16_rn(float lo, float hi) {
    uint32_t r;
    asm("cvt.rn.bf16x2.f32 %0, %1, %2;" : "=r"(r) : "f"(hi), "f"(lo));
    return r;
}

__device__ __forceinline__ void split4(float4 v, uint32_t& h0, uint32_t& h1,
                                       uint32_t& l0, uint32_t& l1) {
    uint32_t bx = __float_as_uint(v.x), by = __float_as_uint(v.y);
    uint32_t bz = __float_as_uint(v.z), bw = __float_as_uint(v.w);
    h0 = __byte_perm(bx, by, 0x7632);
    h1 = __byte_perm(bz, bw, 0x7632);
    float lx = v.x - __uint_as_float(bx & 0xFFFF0000u);
    float ly = v.y - __uint_as_float(by & 0xFFFF0000u);
    float lz = v.z - __uint_as_float(bz & 0xFFFF0000u);
    float lw = v.w - __uint_as_float(bw & 0xFFFF0000u);
    l0 = pack_bf16_rn(lx, ly);
    l1 = pack_bf16_rn(lz, lw);
}

__device__ __forceinline__ void split2(float a, float b, uint32_t& uh, uint32_t& ul) {
    uint32_t ba = __float_as_uint(a), bb = __float_as_uint(b);
    uh = __byte_perm(ba, bb, 0x7632);
    float ra = a - __uint_as_float(ba & 0xFFFF0000u);
    float rb = b - __uint_as_float(bb & 0xFFFF0000u);
    ul = pack_bf16_rn(ra, rb);
}

#define LDSM4(R0, R1, R2, R3, ADDR) \
    asm volatile("ldmatrix.sync.aligned.m8n8.x4.shared.b16 {%0,%1,%2,%3}, [%4];" \
        : "=r"(R0), "=r"(R1), "=r"(R2), "=r"(R3) : "r"(ADDR))

#define LDSM4T(R0, R1, R2, R3, ADDR) \
    asm volatile("ldmatrix.sync.aligned.m8n8.x4.trans.shared.b16 {%0,%1,%2,%3}, [%4];" \
        : "=r"(R0), "=r"(R1), "=r"(R2), "=r"(R3) : "r"(ADDR))

#define MMA16816(CC, A0, A1, A2, A3, B0, B1) \
    asm volatile("mma.sync.aligned.m16n8k16.row.col.f32.bf16.bf16.f32 " \
        "{%0,%1,%2,%3}, {%4,%5,%6,%7}, {%8,%9}, {%0,%1,%2,%3};" \
        : "+f"((CC)[0]), "+f"((CC)[1]), "+f"((CC)[2]), "+f"((CC)[3]) \
        : "r"(A0), "r"(A1), "r"(A2), "r"(A3), "r"(B0), "r"(B1))

#define CPA16(DST, SRC) \
    asm volatile("cp.async.ca.shared.global [%0], [%1], 16;" :: "r"(DST), "l"(SRC) : "memory")
#define CPA_COMMIT() asm volatile("cp.async.commit_group;" ::: "memory")
template<int NN> __device__ __forceinline__ void cpa_wait() {
    asm volatile("cp.async.wait_group %0;" :: "n"(NN) : "memory");
}

#define STS128(ADDR, V) \
    asm volatile("st.shared.v4.b32 [%0], {%1,%2,%3,%4};" \
        :: "r"(ADDR), "r"((V).x), "r"((V).y), "r"((V).z), "r"((V).w) : "memory")
#define STS32(ADDR, V) \
    asm volatile("st.shared.b32 [%0], %1;" :: "r"(ADDR), "r"(V) : "memory")

// ===========================================================================
// fused split kernel: all 5 fp32 inputs -> bf16 hi/lo arrays in ONE launch
// ===========================================================================
#define SEG0 2359296                // x:  4096*2304/4
#define SEG1 (SEG0 + 1179648)       // wq: 2048*2304/4
#define SEG2 (SEG1 + 589824)        // wk: 1024*2304/4
#define SEG3 (SEG2 + 589824)        // wv
#define SEG4 (SEG3 + 1179648)       // wo: 2304*2048/4

__global__ void split_all(
    const float4* __restrict__ x,  const float4* __restrict__ wq,
    const float4* __restrict__ wk, const float4* __restrict__ wv,
    const float4* __restrict__ wo,
    uint2* xh, uint2* xl, uint2* qh, uint2* ql, uint2* kh, uint2* kl,
    uint2* vh, uint2* vl, uint2* oh, uint2* ol)
{
    int i = blockIdx.x * blockDim.x + threadIdx.x;
    if (i >= SEG4) return;
    const float4* s; uint2 *h, *l; int j;
    if (i < SEG0)      { s = x;  h = xh; l = xl; j = i; }
    else if (i < SEG1) { s = wq; h = qh; l = ql; j = i - SEG0; }
    else if (i < SEG2) { s = wk; h = kh; l = kl; j = i - SEG1; }
    else if (i < SEG3) { s = wv; h = vh; l = vl; j = i - SEG2; }
    else               { s = wo; h = oh; l = ol; j = i - SEG3; }
    float4 v = s[j];
    uint32_t h0, h1, l0, l1;
    split4(v, h0, h1, l0, l1);
    h[j] = make_uint2(h0, h1);
    l[j] = make_uint2(l0, l1);
}

// ===========================================================================
// HMMA GEMM (unchanged from R13/R15): 128x128 CTA, BK=64, cp.async 3-stage
// ring, GROUP_M=8 swizzle; QKV segment-select with direct split-v epilogue.
// ===========================================================================
#define GSTAGE  65536
#define GOFF_AL 16384
#define GOFF_BH 32768
#define GOFF_BL 49152

template<bool QKV>
__global__ void __launch_bounds__(256) gemm_b16(
    const __nv_bfloat16* __restrict__ Ah, const __nv_bfloat16* __restrict__ Al,
    const __nv_bfloat16* __restrict__ B0h, const __nv_bfloat16* __restrict__ B0l,
    const __nv_bfloat16* __restrict__ B1h, const __nv_bfloat16* __restrict__ B1l,
    const __nv_bfloat16* __restrict__ B2h, const __nv_bfloat16* __restrict__ B2l,
    float* __restrict__ C, __nv_bfloat16* __restrict__ Ch, __nv_bfloat16* __restrict__ Cl,
    int N, int K)
{
    extern __shared__ unsigned char dsm[];
    uint32_t sb = smem_u32(dsm);
    sb = (sb + 1023u) & ~1023u;

    const int tid  = threadIdx.x;
    const int wid  = tid >> 5;
    const int lane = tid & 31;
    const int wm   = (wid >> 2) * 64;
    const int wn   = (wid & 3) * 32;

    int m0, n0;
    {
        const int nbx = gridDim.x, nby = gridDim.y;
        int pid = blockIdx.y * nbx + blockIdx.x;
        int group = 8 * nbx;
        int gid = pid / group;
        int first_m = gid * 8;
        int gsz = nby - first_m; if (gsz > 8) gsz = 8;
        m0 = (first_m + (pid % group) % gsz) * 128;
        n0 = ((pid % group) / gsz) * 128;
    }
    const int NI = K >> 6;

    const __nv_bfloat16 *Bh, *Bl;
    int nb;
    if (!QKV || n0 < 2048)      { Bh = B0h; Bl = B0l; nb = n0; }
    else if (n0 < 3072)         { Bh = B1h; Bl = B1l; nb = n0 - 2048; }
    else                        { Bh = B2h; Bl = B2l; nb = n0 - 3072; }

    float acc[4][4][4];
#pragma unroll
    for (int mt = 0; mt < 4; mt++)
#pragma unroll
        for (int nt = 0; nt < 4; nt++)
#pragma unroll
            for (int q = 0; q < 4; q++) acc[mt][nt][q] = 0.f;

    const int a_r = (lane & 7) + ((lane >> 3) & 1) * 8;
    const int a_c = (lane >> 4) & 1;
    const int b_r = (lane & 7) + ((lane >> 4) & 1) * 8;
    const int b_c = (lane >> 3) & 1;

    int cr[4], cc[4];
    uint32_t cof[4];
#pragma unroll
    for (int k = 0; k < 4; k++) {
        int idx = tid + k * 256;
        cr[k] = idx >> 3; cc[k] = idx & 7;
        cof[k] = cr[k] * 128 + ((cc[k] ^ (cr[k] & 7)) << 4);
    }

    auto issue = [&](int k0, uint32_t base) {
        const char* pAh = (const char*)Ah + ((size_t)m0 * K + k0) * 2;
        const char* pAl = (const char*)Al + ((size_t)m0 * K + k0) * 2;
        const char* pBh = (const char*)Bh + ((size_t)nb * K + k0) * 2;
        const char* pBl = (const char*)Bl + ((size_t)nb * K + k0) * 2;
#pragma unroll
        for (int k = 0; k < 4; k++) {
            size_t so = (size_t)cr[k] * K * 2 + cc[k] * 16;
            CPA16(base + cof[k],           pAh + so);
            CPA16(base + GOFF_AL + cof[k], pAl + so);
            CPA16(base + GOFF_BH + cof[k], pBh + so);
            CPA16(base + GOFF_BL + cof[k], pBl + so);
        }
        CPA_COMMIT();
    };

    issue(0, sb);
    issue(64, sb + GSTAGE);

    int st = 0;
    for (int it = 0; it < NI; it++) {
        if (it + 1 < NI) cpa_wait<1>(); else cpa_wait<0>();
        __syncthreads();
        if (it + 2 < NI) {
            int st2 = st + 2; if (st2 >= 3) st2 -= 3;
            issue((it + 2) * 64, sb + st2 * GSTAGE);
        }
        const uint32_t sAh = sb + st * GSTAGE;
        const uint32_t sAl = sAh + GOFF_AL;
        const uint32_t sBh = sAh + GOFF_BH;
        const uint32_t sBl = sAh + GOFF_BL;

#pragma unroll
        for (int ks = 0; ks < 4; ks++) {
            const int cb = ks * 2;
            uint32_t ah[4][4], bh[4][2], bl[4][2];

#pragma unroll
            for (int mt = 0; mt < 4; mt++) {
                int r = wm + mt * 16 + a_r;
                uint32_t ad = sAh + r * 128 + (((cb + a_c) ^ (r & 7)) << 4);
                LDSM4(ah[mt][0], ah[mt][1], ah[mt][2], ah[mt][3], ad);
            }
#pragma unroll
            for (int np = 0; np < 2; np++) {
                int r = wn + np * 16 + b_r;
                uint32_t bd = sBh + r * 128 + (((cb + b_c) ^ (r & 7)) << 4);
                LDSM4(bh[2 * np][0], bh[2 * np][1], bh[2 * np + 1][0], bh[2 * np + 1][1], bd);
            }
#pragma unroll
            for (int mt = 0; mt < 4; mt++)
#pragma unroll
                for (int nt = 0; nt < 4; nt++)
                    MMA16816(acc[mt][nt], ah[mt][0], ah[mt][1], ah[mt][2], ah[mt][3],
                             bh[nt][0], bh[nt][1]);
#pragma unroll
            for (int np = 0; np < 2; np++) {
                int r = wn + np * 16 + b_r;
                uint32_t bd = sBl + r * 128 + (((cb + b_c) ^ (r & 7)) << 4);
                LDSM4(bl[2 * np][0], bl[2 * np][1], bl[2 * np + 1][0], bl[2 * np + 1][1], bd);
            }
#pragma unroll
            for (int mt = 0; mt < 4; mt++)
#pragma unroll
                for (int nt = 0; nt < 4; nt++)
                    MMA16816(acc[mt][nt], ah[mt][0], ah[mt][1], ah[mt][2], ah[mt][3],
                             bl[nt][0], bl[nt][1]);
#pragma unroll
            for (int mt = 0; mt < 4; mt++) {
                int r = wm + mt * 16 + a_r;
                uint32_t ad = sAl + r * 128 + (((cb + a_c) ^ (r & 7)) << 4);
                LDSM4(ah[mt][0], ah[mt][1], ah[mt][2], ah[mt][3], ad);
            }
#pragma unroll
            for (int mt = 0; mt < 4; mt++)
#pragma unroll
                for (int nt = 0; nt < 4; nt++)
                    MMA16816(acc[mt][nt], ah[mt][0], ah[mt][1], ah[mt][2], ah[mt][3],
                             bh[nt][0], bh[nt][1]);
        }
        if (++st >= 3) st -= 3;
    }

    const int lr = lane >> 2;
    const int lc = (lane & 3) * 2;
    if (QKV && n0 >= 3072) {
#pragma unroll
        for (int mt = 0; mt < 4; mt++) {
#pragma unroll
            for (int nt = 0; nt < 4; nt++) {
                size_t idx = (size_t)(m0 + wm + mt * 16 + lr) * KV_W +
                             (n0 - 3072) + wn + nt * 8 + lc;
                uint32_t uh, ul;
                split2(acc[mt][nt][0], acc[mt][nt][1], uh, ul);
                *(uint32_t*)(Ch + idx) = uh;
                *(uint32_t*)(Cl + idx) = ul;
                split2(acc[mt][nt][2], acc[mt][nt][3], uh, ul);
                *(uint32_t*)(Ch + idx + 8 * (size_t)KV_W) = uh;
                *(uint32_t*)(Cl + idx + 8 * (size_t)KV_W) = ul;
            }
        }
    } else {
#pragma unroll
        for (int mt = 0; mt < 4; mt++) {
#pragma unroll
            for (int nt = 0; nt < 4; nt++) {
                float* p = C + (size_t)(m0 + wm + mt * 16 + lr) * N + n0 + wn + nt * 8 + lc;
                *(float2*)p           = make_float2(acc[mt][nt][0], acc[mt][nt][1]);
                *(float2*)(p + 8 * N) = make_float2(acc[mt][nt][2], acc[mt][nt][3]);
            }
        }
    }
}

// ---------------------------------------------------------------------------
// Post-QKV: rope+split for q,k (unchanged).
// ---------------------------------------------------------------------------
__global__ void rope_split_qk(const float* __restrict__ qkv, const int* __restrict__ pos,
                              __nv_bfloat16* __restrict__ qh, __nv_bfloat16* __restrict__ ql,
                              __nv_bfloat16* __restrict__ kh, __nv_bfloat16* __restrict__ kl)
{
    const int TQ = S_LEN * NH_Q * 128;
    const int TK = S_LEN * N_KV * 128;
    int i = blockIdx.x * blockDim.x + threadIdx.x;
    if (i >= TQ + TK) return;

    const float* src;
    __nv_bfloat16 *bh, *bl;
    int s, d;
    float scale;
    if (i < TQ) {
        d = i & 127;
        int hh = (i >> 7) & 7;
        s = i >> 10;
        src = qkv + (size_t)s * 4096 + hh * HD_H;
        bh = qh + (size_t)s * QO_W + hh * HD_H;
        bl = ql + (size_t)s * QO_W + hh * HD_H;
        scale = 0.0625f;
    } else {
        int j = i - TQ;
        d = j & 127;
        int hh = (j >> 7) & 3;
        s = j >> 9;
        src = qkv + (size_t)s * 4096 + 2048 + hh * HD_H;
        bh = kh + (size_t)s * KV_W + hh * HD_H;
        bl = kl + (size_t)s * KV_W + hh * HD_H;
        scale = 1.f;
    }
    float p   = (float)pos[s];
    float inv = powf(10000.f, -(float)d * (1.f / 128.f));
    float ang = p * inv;
    float c, sn;
    sincosf(ang, &sn, &c);
    float x1 = src[d];
    float x2 = src[d + 128];
    float y1 = (x1 * c - x2 * sn) * scale;
    float y2 = (x2 * c + x1 * sn) * scale;

    uint32_t b1 = __float_as_uint(y1), b2 = __float_as_uint(y2);
    *(uint16_t*)(bh + d)       = (uint16_t)(b1 >> 16);
    *(uint16_t*)(bh + d + 128) = (uint16_t)(b2 >> 16);
    bl[d]       = __float2bfloat16(y1 - __uint_as_float(b1 & 0xFFFF0000u));
    bl[d + 128] = __float2bfloat16(y2 - __uint_as_float(b2 & 0xFFFF0000u));
}

// ===========================================================================
// Flash attention on HMMA, fixed-max softmax (R15-proven), plus:
//  - cp.async K/V staging with 3-buffer K ring (6 syncs/kt, no reg staging)
//  - PV warp re-grid 2x4 (warp = 32 rows x 64 dims): V LDSM redundancy 4x->2x
// ===========================================================================
#define AOFF_QH  0
#define AOFF_QL  32768
#define AOFF_VH  65536
#define AOFF_VL  98304
#define AOFF_KH  131072    // 3 x 8192
#define AOFF_KL  155648    // 3 x 8192
#define AOFF_PBH 180224    // 8192
#define AOFF_PBL 188416    // 8192
#define AOFF_LS  196608    // 256
#define AOFF_RED 196864    // 512
#define ATTN_SMEM_BYTES (197376 + 128)

__global__ void __launch_bounds__(256) attn_mma(
    const __nv_bfloat16* __restrict__ qh, const __nv_bfloat16* __restrict__ ql,
    const __nv_bfloat16* __restrict__ kh, const __nv_bfloat16* __restrict__ kl,
    const __nv_bfloat16* __restrict__ vh, const __nv_bfloat16* __restrict__ vl,
    __nv_bfloat16* __restrict__ aoh, __nv_bfloat16* __restrict__ aol)
{
    extern __shared__ unsigned char asm_raw[];
    uint32_t sb = smem_u32(asm_raw);
    sb = (sb + 127u) & ~127u;
    const uint32_t pad = sb - smem_u32(asm_raw);

    const uint32_t sQh = sb + AOFF_QH,  sQl = sb + AOFF_QL;
    const uint32_t sVh = sb + AOFF_VH,  sVl = sb + AOFF_VL;
    const uint32_t sKh = sb + AOFF_KH,  sKl = sb + AOFF_KL;
    const uint32_t sPh = sb + AOFF_PBH, sPl = sb + AOFF_PBL;
    float* l_s = (float*)(asm_raw + pad + AOFF_LS);
    float* red = (float*)(asm_raw + pad + AOFF_RED);

    const int tid  = threadIdx.x;
    const int wid  = tid >> 5;
    const int lane = tid & 31;
    const int wr   = wid >> 1;           // QK: 4 row groups of 16
    const int wc   = wid & 1;            // QK: 2 key halves of 32
    const int wr2  = wid >> 2;           // PV: 2 row groups of 32
    const int wc2  = wid & 3;            // PV: 4 dim groups of 64
    const int qt   = gridDim.x - 1 - blockIdx.x;
    const int h    = blockIdx.y;
    const int qs   = qt * 64;
    const int kvh  = h >> 1;
    const float CAP = 50.f, INV_CAP2 = 2.f / 50.f;

    const int a_r = (lane & 7) + ((lane >> 3) & 1) * 8;
    const int a_c = (lane >> 4) & 1;
    const int b_r = (lane & 7) + ((lane >> 4) & 1) * 8;
    const int b_c = (lane >> 3) & 1;
    const int lr  = lane >> 2;
    const int lc  = (lane & 3) * 2;
    const int l4  = lane & 3;

    // ---- load pre-split Q (64 x 256 bf16, already scaled) ----
    {
        const char* qhb = (const char*)(qh + (size_t)qs * QO_W + h * HD_H);
        const char* qlb = (const char*)(ql + (size_t)qs * QO_W + h * HD_H);
#pragma unroll
        for (int i = 0; i < 8; i++) {
            int idx = tid + i * 256;
            int r = idx >> 5, c = idx & 31;
            uint32_t off = r * 512 + ((c ^ (r & 7)) << 4);
            uint4 vh4 = *(const uint4*)(qhb + (size_t)r * QO_W * 2 + c * 16);
            uint4 vl4 = *(const uint4*)(qlb + (size_t)r * QO_W * 2 + c * 16);
            STS128(sQh + off, vh4);
            STS128(sQl + off, vl4);
        }
    }
    if (tid < 64) l_s[tid] = 0.f;

    // O accumulator: PV grid, rows wr2*32..+32 (2 m16), dims wc2*64..+64 (8 n8)
    float o[2][8][4];
#pragma unroll
    for (int mt = 0; mt < 2; mt++)
#pragma unroll
        for (int nt = 0; nt < 8; nt++)
#pragma unroll
            for (int q = 0; q < 4; q++) o[mt][nt][q] = 0.f;

    const int kt_lo = (qs - (SWIN - 1) > 0 ? qs - (SWIN - 1) : 0) >> 6;
    const __nv_bfloat16* khb0 = kh + kvh * HD_H;
    const __nv_bfloat16* klb0 = kl + kvh * HD_H;
    const __nv_bfloat16* vhb0 = vh + kvh * HD_H;
    const __nv_bfloat16* vlb0 = vl + kvh * HD_H;

    // cp.async staging coords: 64 rows x 8 chunks x 2 rows/thread
    const int s_r = tid >> 3, s_c = tid & 7;
    const int s_r1 = (tid + 256) >> 3, s_c1 = (tid + 256) & 7;
    const uint32_t offk0_sw = s_r * 128 + ((s_c ^ (s_r & 7)) << 4);
    const uint32_t offk1_sw = s_r1 * 128 + ((s_c1 ^ (s_r1 & 7)) << 4);

    int kb0 = 0;   // K ring base (mod 3); +1 per kt (4 chunks mod 3)

    for (int kt = qt; kt >= kt_lo; kt--) {
        const int ks0 = kt * 64;
        const char* khr = (const char*)(khb0 + (size_t)ks0 * KV_W);
        const char* klr = (const char*)(klb0 + (size_t)ks0 * KV_W);
        const char* vhr = (const char*)(vhb0 + (size_t)ks0 * KV_W);
        const char* vlr = (const char*)(vlb0 + (size_t)ks0 * KV_W);

        auto issue = [&](int dc, int kb) {
            size_t go0 = (size_t)s_r  * (KV_W * 2) + dc * 128 + s_c  * 16;
            size_t go1 = (size_t)s_r1 * (KV_W * 2) + dc * 128 + s_c1 * 16;
            uint32_t kbase = kb * 8192;
            uint32_t offv0 = s_r  * 512 + (((dc * 8 + s_c)  ^ (s_r  & 7)) << 4);
            uint32_t offv1 = s_r1 * 512 + (((dc * 8 + s_c1) ^ (s_r1 & 7)) << 4);
            CPA16(sKh + kbase + offk0_sw, khr + go0);
            CPA16(sKh + kbase + offk1_sw, khr + go1);
            CPA16(sKl + kbase + offk0_sw, klr + go0);
            CPA16(sKl + kbase + offk1_sw, klr + go1);
            CPA16(sVh + offv0, vhr + go0);
            CPA16(sVh + offv1, vhr + go1);
            CPA16(sVl + offv0, vlr + go0);
            CPA16(sVl + offv1, vlr + go1);
            CPA_COMMIT();
        };

        float s[4][4];
#pragma unroll
        for (int nt = 0; nt < 4; nt++)
#pragma unroll
            for (int q = 0; q < 4; q++) s[nt][q] = 0.f;

        __syncthreads();   // prev kt PV done reading V/P; K ring safe by iter spacing
        issue(0, kb0);

#pragma unroll
        for (int dc = 0; dc < 4; dc++) {
            if (dc < 3) {
                int kbn = kb0 + dc + 1; if (kbn >= 3) kbn -= 3; if (kbn >= 3) kbn -= 3;
                issue(dc + 1, kbn);
                cpa_wait<1>();
            } else {
                cpa_wait<0>();
            }
            __syncthreads();   // chunk dc visible to all

            int kbc = kb0 + dc; if (kbc >= 3) kbc -= 3; if (kbc >= 3) kbc -= 3;
            const uint32_t kB = kbc * 8192;
#pragma unroll
            for (int ks = 0; ks < 4; ks++) {
                const int cbq = dc * 8 + ks * 2;
                const int cbk = ks * 2;
                uint32_t ah[4], al[4], bh[2][4], bl[4];
                {
                    int r = wr * 16 + a_r;
                    LDSM4(ah[0], ah[1], ah[2], ah[3],
                          sQh + r * 512 + (((cbq + a_c) ^ (r & 7)) << 4));
                    LDSM4(al[0], al[1], al[2], al[3],
                          sQl + r * 512 + (((cbq + a_c) ^ (r & 7)) << 4));
                }
#pragma unroll
                for (int np = 0; np < 2; np++) {
                    int r = wc * 32 + np * 16 + b_r;
                    LDSM4(bh[np][0], bh[np][1], bh[np][2], bh[np][3],
                          sKh + kB + r * 128 + (((cbk + b_c) ^ (r & 7)) << 4));
                }
#pragma unroll
                for (int np = 0; np < 2; np++) {
                    MMA16816(s[2 * np],     ah[0], ah[1], ah[2], ah[3], bh[np][0], bh[np][1]);
                    MMA16816(s[2 * np + 1], ah[0], ah[1], ah[2], ah[3], bh[np][2], bh[np][3]);
                    MMA16816(s[2 * np],     al[0], al[1], al[2], al[3], bh[np][0], bh[np][1]);
                    MMA16816(s[2 * np + 1], al[0], al[1], al[2], al[3], bh[np][2], bh[np][3]);
                }
#pragma unroll
                for (int np = 0; np < 2; np++) {
                    int r = wc * 32 + np * 16 + b_r;
                    LDSM4(bl[0], bl[1], bl[2], bl[3],
                          sKl + kB + r * 128 + (((cbk + b_c) ^ (r & 7)) << 4));
                    MMA16816(s[2 * np],     ah[0], ah[1], ah[2], ah[3], bl[0], bl[1]);
                    MMA16816(s[2 * np + 1], ah[0], ah[1], ah[2], ah[3], bl[2], bl[3]);
                }
            }
        }
        kb0++; if (kb0 >= 3) kb0 -= 3;

        // ---- fixed-max softmax in regs: e = exp(softcap(s) - CAP) ----
        {
            float sums[2] = {0.f, 0.f};
#pragma unroll
            for (int nt = 0; nt < 4; nt++) {
                int col = wc * 32 + nt * 8 + lc;
                int gj0 = ks0 + col;
#pragma unroll
                for (int half = 0; half < 2; half++) {
                    int row = wr * 16 + lr + half * 8;
                    int gi = qs + row;
                    float t0 = __expf(s[nt][2 * half + 0] * INV_CAP2);
                    float t1 = __expf(s[nt][2 * half + 1] * INV_CAP2);
                    float e0 = __expf(-__fdividef(2.f * CAP, t0 + 1.f));
                    float e1 = __expf(-__fdividef(2.f * CAP, t1 + 1.f));
                    bool ok0 = (gj0 <= gi)     && ((gi - gj0) < SWIN);
                    bool ok1 = (gj0 + 1 <= gi) && ((gi - gj0 - 1) < SWIN);
                    e0 = ok0 ? e0 : 0.f;
                    e1 = ok1 ? e1 : 0.f;
                    sums[half] += e0 + e1;
                    uint32_t ph, pl;
                    split2(e0, e1, ph, pl);
                    uint32_t off = row * 128 +
                        ((((uint32_t)(wc * 4 + nt)) ^ (row & 7)) << 4) + lc * 2;
                    STS32(sPh + off, ph);
                    STS32(sPl + off, pl);
                }
            }
#pragma unroll
            for (int mk = 1; mk <= 2; mk <<= 1) {
                sums[0] += __shfl_xor_sync(0xFFFFFFFFu, sums[0], mk);
                sums[1] += __shfl_xor_sync(0xFFFFFFFFu, sums[1], mk);
            }
            if (l4 == 0) {
                red[(wr * 16 + lr) * 2 + wc]     = sums[0];
                red[(wr * 16 + lr + 8) * 2 + wc] = sums[1];
            }
        }
        __syncthreads();   // P stores + red visible
        if (tid < 64) l_s[tid] += red[tid * 2] + red[tid * 2 + 1];

        // ---- O += P V  (PV grid 2x4; 3-term: Ph*Vh + Pl*Vh + Ph*Vl) ----
#pragma unroll
        for (int kk = 0; kk < 4; kk++) {
            uint32_t ph[2][4], pl[2][4];
#pragma unroll
            for (int mt = 0; mt < 2; mt++) {
                int r = wr2 * 32 + mt * 16 + a_r;
                uint32_t c = kk * 2 + a_c;
                LDSM4(ph[mt][0], ph[mt][1], ph[mt][2], ph[mt][3],
                      sPh + r * 128 + ((c ^ (r & 7)) << 4));
                LDSM4(pl[mt][0], pl[mt][1], pl[mt][2], pl[mt][3],
                      sPl + r * 128 + ((c ^ (r & 7)) << 4));
            }
#pragma unroll
            for (int vp = 0; vp < 4; vp++) {
                int key = kk * 16 + a_r;
                uint32_t chv = wc2 * 8 + vp * 2 + a_c;
                uint32_t vb[4], vl4[4];
                LDSM4T(vb[0], vb[1], vb[2], vb[3],
                       sVh + key * 512 + ((chv ^ (key & 7)) << 4));
#pragma unroll
                for (int mt = 0; mt < 2; mt++) {
                    MMA16816(o[mt][2 * vp],     ph[mt][0], ph[mt][1], ph[mt][2], ph[mt][3],
                             vb[0], vb[1]);
                    MMA16816(o[mt][2 * vp + 1], ph[mt][0], ph[mt][1], ph[mt][2], ph[mt][3],
                             vb[2], vb[3]);
                    MMA16816(o[mt][2 * vp],     pl[mt][0], pl[mt][1], pl[mt][2], pl[mt][3],
                             vb[0], vb[1]);
                    MMA16816(o[mt][2 * vp + 1], pl[mt][0], pl[mt][1], pl[mt][2], pl[mt][3],
                             vb[2], vb[3]);
                }
                LDSM4T(vl4[0], vl4[1], vl4[2], vl4[3],
                       sVl + key * 512 + ((chv ^ (key & 7)) << 4));
#pragma unroll
                for (int mt = 0; mt < 2; mt++) {
                    MMA16816(o[mt][2 * vp],     ph[mt][0], ph[mt][1], ph[mt][2], ph[mt][3],
                             vl4[0], vl4[1]);
                    MMA16816(o[mt][2 * vp + 1], ph[mt][0], ph[mt][1], ph[mt][2], ph[mt][3],
                             vl4[2], vl4[3]);
                }
            }
        }
    }

    __syncthreads();
    // ---- normalize + split + write bf16 (PV grid) ----
#pragma unroll
    for (int mt = 0; mt < 2; mt++) {
        int rbase = wr2 * 32 + mt * 16 + lr;
        float inva = 1.f / l_s[rbase];
        float invb = 1.f / l_s[rbase + 8];
        size_t i0 = (size_t)(qs + rbase) * QO_W + h * HD_H + wc2 * 64;
        size_t i1 = i0 + 8 * (size_t)QO_W;
#pragma unroll
        for (int nt = 0; nt < 8; nt++) {
            uint32_t uh, ul;
            split2(o[mt][nt][0] * inva, o[mt][nt][1] * inva, uh, ul);
            *(uint32_t*)(aoh + i0 + nt * 8 + lc) = uh;
            *(uint32_t*)(aol + i0 + nt * 8 + lc) = ul;
            split2(o[mt][nt][2] * invb, o[mt][nt][3] * invb, uh, ul);
            *(uint32_t*)(aoh + i1 + nt * 8 + lc) = uh;
            *(uint32_t*)(aol + i1 + nt * 8 + lc) = ul;
        }
    }
}

// ---------------------------------------------------------------------------
// Launch
// ---------------------------------------------------------------------------
#define GEMM_DSMEM (3 * GSTAGE + 1024)

extern "C" void kernel_launch(void* const* d_in, const int* in_sizes, int n_in,
                              void* d_out, int out_size)
{
    const float* x   = (const float*)d_in[0];   // [4096, 2304]
    const int*   pos = (const int*)  d_in[1];   // [1, 4096]
    const float* Wq  = (const float*)d_in[2];   // [2048, 2304]
    const float* Wk  = (const float*)d_in[3];   // [1024, 2304]
    const float* Wv  = (const float*)d_in[4];   // [1024, 2304]
    const float* Wo  = (const float*)d_in[5];   // [2304, 2048]
    float* out = (float*)d_out;                 // [4096, 2304]

    float* qkv;
    __nv_bfloat16 *xh, *xl, *wqh, *wql, *wkh, *wkl, *wvh, *wvl, *woh, *wol;
    __nv_bfloat16 *qh, *ql, *kh2, *kl2, *vh, *vl, *aoh, *aol;
    cudaGetSymbolAddress((void**)&qkv, g_qkv);
    cudaGetSymbolAddress((void**)&xh,  g_xh);  cudaGetSymbolAddress((void**)&xl,  g_xl);
    cudaGetSymbolAddress((void**)&wqh, g_wqh); cudaGetSymbolAddress((void**)&wql, g_wql);
    cudaGetSymbolAddress((void**)&wkh, g_wkh); cudaGetSymbolAddress((void**)&wkl, g_wkl);
    cudaGetSymbolAddress((void**)&wvh, g_wvh); cudaGetSymbolAddress((void**)&wvl, g_wvl);
    cudaGetSymbolAddress((void**)&woh, g_woh); cudaGetSymbolAddress((void**)&wol, g_wol);
    cudaGetSymbolAddress((void**)&qh,  g_qh);  cudaGetSymbolAddress((void**)&ql,  g_ql);
    cudaGetSymbolAddress((void**)&kh2, g_kh);  cudaGetSymbolAddress((void**)&kl2, g_kl);
    cudaGetSymbolAddress((void**)&vh,  g_vh);  cudaGetSymbolAddress((void**)&vl,  g_vl);
    cudaGetSymbolAddress((void**)&aoh, g_aoh); cudaGetSymbolAddress((void**)&aol, g_aol);

    cudaFuncSetAttribute(gemm_b16<true>,  cudaFuncAttributeMaxDynamicSharedMemorySize, GEMM_DSMEM);
    cudaFuncSetAttribute(gemm_b16<false>, cudaFuncAttributeMaxDynamicSharedMemorySize, GEMM_DSMEM);
    cudaFuncSetAttribute(attn_mma, cudaFuncAttributeMaxDynamicSharedMemorySize, ATTN_SMEM_BYTES);

    // One fused split of all fp32 inputs
    split_all<<<(SEG4 + 255) / 256, 256>>>(
        (const float4*)x, (const float4*)Wq, (const float4*)Wk,
        (const float4*)Wv, (const float4*)Wo,
        (uint2*)xh, (uint2*)xl, (uint2*)wqh, (uint2*)wql,
        (uint2*)wkh, (uint2*)wkl, (uint2*)wvh, (uint2*)wvl,
        (uint2*)woh, (uint2*)wol);

    // Fused QKV projection: q,k -> fp32 g_qkv; v -> split bf16 directly
    gemm_b16<true><<<dim3(32, 32), 256, GEMM_DSMEM>>>(
        xh, xl, wqh, wql, wkh, wkl, wvh, wvl, qkv, vh, vl, 4096, HID_D);

    // RoPE + scale + split (q,k)
    {
        int total = S_LEN * (NH_Q + N_KV) * 128;
        rope_split_qk<<<(total + 255) / 256, 256>>>(qkv, pos, qh, ql, kh2, kl2);
    }

    // Flash attention (HMMA, fixed-max softmax, cp.async staging, split bf16)
    attn_mma<<<dim3(S_LEN / 64, NH_Q), 256, ATTN_SMEM_BYTES>>>(
        qh, ql, kh2, kl2, vh, vl, aoh, aol);

    // Output projection
    gemm_b16<false><<<dim3(18, 32), 256, GEMM_DSMEM>>>(
        aoh, aol, woh, wol, woh, wol, woh, wol, out, nullptr, nullptr, HID_D, QO_W);
}